// round 10
// baseline (speedup 1.0000x reference)
#include <cuda_runtime.h>
#include <cuda_bf16.h>
#include <cstdint>
#include <math.h>

constexpr int B_  = 4;
constexpr int C_  = 256;
constexpr int C8_ = 32;
constexpr int N_  = 4096;
constexpr int K_  = 3;

constexpr int TI = 128;   // queries per CTA
constexpr int TJ = 64;    // keys per j-step
constexpr int TC = 128;   // channels per CTA (split across blockIdx.y)
constexpr int NSTEP = N_ / TJ;

// ---- scratch (device globals; no allocation allowed) ----------------------
__device__ __nv_bfloat16 g_q[(size_t)K_ * B_ * N_ * C8_];   // [kk*B+b][n][o]
__device__ __nv_bfloat16 g_k[(size_t)B_ * N_ * C8_];        // [b][n][o]
__device__ uint8_t       g_v[(size_t)K_ * B_ * C_ * N_];    // [kk*B+b][c][n] e4m3
__device__ float         g_acc[(size_t)B_ * C_ * N_];       // [b][c][n]

// ---- helpers --------------------------------------------------------------
__device__ __forceinline__ uint32_t smem_u32(const void* p) {
    uint32_t a;
    asm("{ .reg .u64 t; cvta.to.shared.u64 t, %1; cvt.u32.u64 %0, t; }" : "=r"(a) : "l"(p));
    return a;
}
__device__ __forceinline__ void ldsm4(uint32_t* r, uint32_t addr) {
    asm volatile("ldmatrix.sync.aligned.m8n8.x4.shared.b16 {%0,%1,%2,%3}, [%4];"
                 : "=r"(r[0]), "=r"(r[1]), "=r"(r[2]), "=r"(r[3]) : "r"(addr));
}
__device__ __forceinline__ void mma16816(float* d, const uint32_t* a, uint32_t b0, uint32_t b1) {
    asm volatile("mma.sync.aligned.m16n8k16.row.col.f32.bf16.bf16.f32 "
                 "{%0,%1,%2,%3}, {%4,%5,%6,%7}, {%8,%9}, {%0,%1,%2,%3};"
                 : "+f"(d[0]), "+f"(d[1]), "+f"(d[2]), "+f"(d[3])
                 : "r"(a[0]), "r"(a[1]), "r"(a[2]), "r"(a[3]), "r"(b0), "r"(b1));
}
__device__ __forceinline__ void mma16832f8(float* d, const uint32_t* a, uint32_t b0, uint32_t b1) {
    asm volatile("mma.sync.aligned.m16n8k32.row.col.f32.e4m3.e4m3.f32 "
                 "{%0,%1,%2,%3}, {%4,%5,%6,%7}, {%8,%9}, {%0,%1,%2,%3};"
                 : "+f"(d[0]), "+f"(d[1]), "+f"(d[2]), "+f"(d[3])
                 : "r"(a[0]), "r"(a[1]), "r"(a[2]), "r"(a[3]), "r"(b0), "r"(b1));
}
__device__ __forceinline__ uint32_t packbf2(float x, float y) {
    __nv_bfloat162 h = __float22bfloat162_rn(make_float2(x, y));
    return *(uint32_t*)&h;
}
__device__ __forceinline__ uint16_t pack2_e4m3(float f0, float f1) {
    uint16_t r;
    asm("cvt.rn.satfinite.e4m3x2.f32 %0, %1, %2;" : "=h"(r) : "f"(f1), "f"(f0));
    return r;
}
__device__ __forceinline__ void cp16(uint32_t dst, const void* src) {
    asm volatile("cp.async.cg.shared.global [%0], [%1], 16;" :: "r"(dst), "l"(src));
}
#define CP_COMMIT() asm volatile("cp.async.commit_group;" ::: "memory")
#define CP_WAIT1()  asm volatile("cp.async.wait_group 1;" ::: "memory")

// ---- smem layout ----------------------------------------------------------
constexpr int QROW = 80;    // 64B bf16 data + 16B pad
constexpr int KROW = 80;
constexpr int VROW = 80;    // 64B e4m3 data + 16B pad
constexpr int PROW = 80;    // 64B e4m3 P data + 16B pad
constexpr int SM_Q  = 0;                       // 128 * 80 = 10240
constexpr int SM_P  = 10240;                   // 4 warps * 32 * 80 = 10240
constexpr int SM_K0 = 20480;
constexpr int VOFF  = 64 * KROW;               // V base within buffer
constexpr int BUFD  = 64 * KROW + TC * VROW;   // 15360
constexpr int SM_TOTAL = SM_K0 + 2 * BUFD;     // 51200

// ---------------------------------------------------------------------------
// attention: 128 threads, 4 warps, M=32 rows/warp; GEMM1 bf16, GEMM2 e4m3
__global__ void __launch_bounds__(128, 2) attn_kernel() {
    extern __shared__ char smem[];
    uint32_t sb = smem_u32(smem);
    int tid = threadIdx.x, wid = tid >> 5, lane = tid & 31;
    int g = lane >> 2, m = lane & 3;
    int b = blockIdx.z;
    int cbase = blockIdx.y * TC;
    int itile = blockIdx.x * TI;
    int wrow = wid * 32;

    uint32_t qaddr = sb + SM_Q + (wrow + (lane & 15)) * QROW + ((lane >> 4) & 1) * 16;
    uint32_t koff = ((lane >> 4) * 8 + (lane & 7)) * KROW + ((lane >> 3) & 1) * 16;
    // V (e4m3) ldmatrix: tiles [c0-7,k0-15][c0-7,k16-31][c8-15,k0-15][c8-15,k16-31]
    uint32_t voff = VOFF + (((lane >> 4) & 1) * 8 + (lane & 7)) * VROW + ((lane >> 3) & 1) * 16;
    // per-warp P tile base + ldmatrix A-frag address
    uint32_t pwbase = sb + SM_P + wid * 32 * PROW;
    uint32_t paddr = pwbase + (((lane >> 3) & 1) * 8 + (lane & 7)) * PROW + (lane >> 4) * 16;

    const __nv_bfloat16* kbase = g_k + (size_t)b * N_ * C8_;

    for (int kk = 0; kk < K_; kk++) {
        size_t zb = (size_t)kk * B_ + b;
        const uint8_t* vbase = g_v + (zb * C_ + cbase) * (size_t)N_;
        __syncthreads();
        // Q tile -> smem (128 rows x 64B)
        const __nv_bfloat16* qp = g_q + (zb * N_ + itile) * C8_;
        for (int t = tid; t < 512; t += 128) {
            int r = t >> 2, ch = t & 3;
            *(uint4*)(smem + SM_Q + r * QROW + ch * 16) = *(const uint4*)(qp + r * C8_ + ch * 8);
        }

        // prologue: async-load K,V tile 0 into buffer 0
        {
            uint32_t bufb = sb + SM_K0;
#pragma unroll
            for (int i = 0; i < 2; i++) {
                int t = tid + 128 * i;
                int r = t >> 2, ch = t & 3;
                cp16(bufb + r * KROW + ch * 16, kbase + (size_t)r * C8_ + ch * 8);
            }
#pragma unroll
            for (int i = 0; i < 4; i++) {
                int t = tid + 128 * i;
                int c = t >> 2, ch = t & 3;
                cp16(bufb + VOFF + c * VROW + ch * 16, vbase + (size_t)c * N_ + ch * 16);
            }
            CP_COMMIT();
        }

        __syncthreads();
        uint32_t qa[2][2][4];
#pragma unroll
        for (int t = 0; t < 2; t++) {
            ldsm4(qa[t][0], qaddr + t * 16 * QROW);
            ldsm4(qa[t][1], qaddr + t * 16 * QROW + 32);
        }

        float Dn[2][16][4];
#pragma unroll
        for (int t = 0; t < 2; t++)
#pragma unroll
            for (int c = 0; c < 16; c++)
#pragma unroll
                for (int p = 0; p < 4; p++) Dn[t][c][p] = 0.f;
        float den[2][2] = {{0.f, 0.f}, {0.f, 0.f}};

        for (int js = 0; js < NSTEP; js++) {
            uint32_t bufb = sb + SM_K0 + (js & 1) * BUFD;
            if (js + 1 < NSTEP) {
                int jt2 = (js + 1) * TJ;
                uint32_t nb = sb + SM_K0 + ((js + 1) & 1) * BUFD;
#pragma unroll
                for (int i = 0; i < 2; i++) {
                    int t = tid + 128 * i;
                    int r = t >> 2, ch = t & 3;
                    cp16(nb + r * KROW + ch * 16, kbase + (size_t)(jt2 + r) * C8_ + ch * 8);
                }
#pragma unroll
                for (int i = 0; i < 4; i++) {
                    int t = tid + 128 * i;
                    int c = t >> 2, ch = t & 3;
                    cp16(nb + VOFF + c * VROW + ch * 16, vbase + (size_t)c * N_ + jt2 + ch * 16);
                }
            }
            CP_COMMIT();
            CP_WAIT1();
            __syncthreads();

            // ---- GEMM1 (bf16): S[32 x 64] = Q . K^T ----
            float s[2][8][4];
#pragma unroll
            for (int t = 0; t < 2; t++)
#pragma unroll
                for (int j = 0; j < 8; j++)
#pragma unroll
                    for (int p = 0; p < 4; p++) s[t][j][p] = 0.f;
#pragma unroll
            for (int kc = 0; kc < 2; kc++) {
#pragma unroll
                for (int jp = 0; jp < 4; jp++) {
                    uint32_t kb[4];
                    ldsm4(kb, bufb + koff + jp * 16 * KROW + kc * 32);
#pragma unroll
                    for (int t = 0; t < 2; t++) {
                        mma16816(s[t][2 * jp],     qa[t][kc], kb[0], kb[1]);
                        mma16816(s[t][2 * jp + 1], qa[t][kc], kb[2], kb[3]);
                    }
                }
            }
            // ---- exp -> e4m3 P tile in per-warp smem; fp32 denominators ----
#pragma unroll
            for (int t = 0; t < 2; t++) {
#pragma unroll
                for (int jp = 0; jp < 8; jp++) {
                    float e0 = __expf(s[t][jp][0]), e1 = __expf(s[t][jp][1]);
                    float e2 = __expf(s[t][jp][2]), e3 = __expf(s[t][jp][3]);
                    den[t][0] += e0 + e1;
                    den[t][1] += e2 + e3;
                    uint16_t lo = pack2_e4m3(e0, e1);
                    uint16_t hi = pack2_e4m3(e2, e3);
                    uint32_t a0 = pwbase + (t * 16 + g) * PROW + jp * 8 + 2 * m;
                    asm volatile("st.shared.u16 [%0], %1;" :: "r"(a0), "h"(lo));
                    asm volatile("st.shared.u16 [%0], %1;" :: "r"(a0 + 8 * PROW), "h"(hi));
                }
            }
            __syncwarp();

            // A-fragments for both Mtiles x both k32 chunks
            uint32_t af[2][2][4];
#pragma unroll
            for (int t = 0; t < 2; t++)
#pragma unroll
                for (int c = 0; c < 2; c++)
                    ldsm4(af[t][c], paddr + t * 16 * PROW + c * 32);

            // ---- GEMM2 (e4m3): D[32 x TC] += P . V^T ----
#pragma unroll
            for (int c = 0; c < 2; c++) {
#pragma unroll
                for (int vp = 0; vp < 8; vp++) {
                    uint32_t vb[4];
                    ldsm4(vb, bufb + voff + vp * 16 * VROW + c * 32);
#pragma unroll
                    for (int t = 0; t < 2; t++) {
                        mma16832f8(Dn[t][2 * vp],     af[t][c], vb[0], vb[1]);
                        mma16832f8(Dn[t][2 * vp + 1], af[t][c], vb[2], vb[3]);
                    }
                }
            }
            __syncthreads();
        }

        // denominators: reduce over the 4 lanes of each row
        float inv[2][2];
#pragma unroll
        for (int t = 0; t < 2; t++)
#pragma unroll
            for (int h = 0; h < 2; h++) {
                float d = den[t][h];
                d += __shfl_xor_sync(0xffffffffu, d, 1);
                d += __shfl_xor_sync(0xffffffffu, d, 2);
                inv[t][h] = 1.f / d;
            }

        // normalize + accumulate into g_acc[b][c][n]
        float* accb = g_acc + (size_t)b * C_ * N_;
        int cb0 = cbase + 2 * m;
#pragma unroll
        for (int t = 0; t < 2; t++) {
            int n0 = itile + wrow + t * 16 + g;
#pragma unroll
            for (int ct = 0; ct < 16; ct++) {
                int c = cb0 + 8 * ct;
                float* p0 = accb + (size_t)c * N_ + n0;
                float* p1 = p0 + N_;
                float v0 = Dn[t][ct][0] * inv[t][0], v1 = Dn[t][ct][1] * inv[t][0];
                float v2 = Dn[t][ct][2] * inv[t][1], v3 = Dn[t][ct][3] * inv[t][1];
                if (kk == 0) {
                    p0[0] = v0; p1[0] = v1; p0[8] = v2; p1[8] = v3;
                } else {
                    p0[0] += v0; p1[0] += v1; p0[8] += v2; p1[8] += v3;
                }
            }
        }
    }
}

// ---------------------------------------------------------------------------
// q/k projection via bf16 tensor cores: out[z][n][o] (o=32) = x^T.W^T + b
constexpr int PXROW = 144;
constexpr int PWROW = 144;

__global__ void __launch_bounds__(128, 4) proj_qk_kernel(const float* __restrict__ x,
                                                         const float* __restrict__ W,
                                                         const float* __restrict__ bias,
                                                         int which) {
    __shared__ char sm[128 * PXROW + 32 * PWROW];
    uint32_t xt_b = smem_u32(sm);
    uint32_t wt_b = xt_b + 128 * PXROW;
    int tid = threadIdx.x, wid = tid >> 5, lane = tid & 31;
    int z = blockIdx.z;
    int n0 = blockIdx.x * 128;
    int wrow = wid * 32;
    const float* xb = x + (size_t)z * C_ * N_;

    uint32_t xaddr = xt_b + (wrow + (lane & 15)) * PXROW + ((lane >> 4) & 1) * 16;
    uint32_t waddr = wt_b + ((lane >> 4) * 8 + (lane & 7)) * PWROW + ((lane >> 3) & 1) * 16;

    float s[2][4][4];
#pragma unroll
    for (int t = 0; t < 2; t++)
#pragma unroll
        for (int j = 0; j < 4; j++) {
            int o = j * 8 + 2 * (lane & 3);
            float b0 = bias[o], b1 = bias[o + 1];
            s[t][j][0] = b0; s[t][j][1] = b1;
            s[t][j][2] = b0; s[t][j][3] = b1;
        }

    for (int ks = 0; ks < 4; ks++) {
        int k0 = ks * 64;
        __syncthreads();
        {
            int n = tid;
#pragma unroll
            for (int kg = 0; kg < 16; kg++) {
                int k = k0 + kg * 4;
                float a0 = xb[(size_t)(k + 0) * N_ + n0 + n];
                float a1 = xb[(size_t)(k + 1) * N_ + n0 + n];
                float a2 = xb[(size_t)(k + 2) * N_ + n0 + n];
                float a3 = xb[(size_t)(k + 3) * N_ + n0 + n];
                uint32_t lo = packbf2(a0, a1), hi = packbf2(a2, a3);
                uint32_t d = xt_b + n * PXROW + kg * 8;
                asm volatile("st.shared.v2.b32 [%0], {%1, %2};" :: "r"(d), "r"(lo), "r"(hi));
            }
        }
#pragma unroll
        for (int i = 0; i < 4; i++) {
            int e = tid + 128 * i;
            int r = e >> 4, kq = e & 15;
            float4 w4 = *(const float4*)(W + (size_t)r * C_ + k0 + kq * 4);
            uint32_t lo = packbf2(w4.x, w4.y), hi = packbf2(w4.z, w4.w);
            uint32_t d = wt_b + r * PWROW + kq * 8;
            asm volatile("st.shared.v2.b32 [%0], {%1, %2};" :: "r"(d), "r"(lo), "r"(hi));
        }
        __syncthreads();

#pragma unroll
        for (int kc = 0; kc < 4; kc++) {
            uint32_t qa[2][4];
#pragma unroll
            for (int t = 0; t < 2; t++)
                ldsm4(qa[t], xaddr + t * 16 * PXROW + kc * 32);
#pragma unroll
            for (int jp = 0; jp < 2; jp++) {
                uint32_t wb[4];
                ldsm4(wb, waddr + jp * 16 * PWROW + kc * 32);
#pragma unroll
                for (int t = 0; t < 2; t++) {
                    mma16816(s[t][2 * jp],     qa[t], wb[0], wb[1]);
                    mma16816(s[t][2 * jp + 1], qa[t], wb[2], wb[3]);
                }
            }
        }
    }

    __nv_bfloat16* dst = (which ? g_k : g_q) + ((size_t)z * N_ + n0) * C8_;
#pragma unroll
    for (int t = 0; t < 2; t++) {
        int n = wrow + t * 16 + (lane >> 2);
#pragma unroll
        for (int j = 0; j < 4; j++) {
            int o = j * 8 + 2 * (lane & 3);
            *(uint32_t*)(dst + (size_t)n * C8_ + o)       = packbf2(s[t][j][0], s[t][j][1]);
            *(uint32_t*)(dst + (size_t)(n + 8) * C8_ + o) = packbf2(s[t][j][2], s[t][j][3]);
        }
    }
}

// ---------------------------------------------------------------------------
// v projection via bf16 tensor cores, output e4m3: g_v[z][c][n]
constexpr int WROW = 144;
constexpr int XROW = 144;

__global__ void __launch_bounds__(128, 2) proj_v_kernel(const float* __restrict__ xball,
                                                        const float* __restrict__ W,
                                                        const float* __restrict__ bias) {
    __shared__ char sm[128 * WROW + 128 * XROW];
    uint32_t wt_b = smem_u32(sm);
    uint32_t xt_b = wt_b + 128 * WROW;
    int tid = threadIdx.x, wid = tid >> 5, lane = tid & 31;
    int z = blockIdx.z;
    int cbase = blockIdx.y * 128;
    int n0 = blockIdx.x * 128;
    int wrow = wid * 32;
    const float* xb = xball + (size_t)z * C_ * N_;

    uint32_t waddr = wt_b + (wrow + (lane & 15)) * WROW + ((lane >> 4) & 1) * 16;
    uint32_t xaddr = xt_b + ((lane >> 4) * 8 + (lane & 7)) * XROW + ((lane >> 3) & 1) * 16;

    float acc[2][16][4];
#pragma unroll
    for (int t = 0; t < 2; t++) {
        float b0 = bias[cbase + wrow + t * 16 + (lane >> 2)];
        float b1 = bias[cbase + wrow + t * 16 + (lane >> 2) + 8];
#pragma unroll
        for (int nt = 0; nt < 16; nt++) {
            acc[t][nt][0] = b0; acc[t][nt][1] = b0;
            acc[t][nt][2] = b1; acc[t][nt][3] = b1;
        }
    }

    for (int ks = 0; ks < 4; ks++) {
        int k0 = ks * 64;
        __syncthreads();
#pragma unroll
        for (int i = 0; i < 16; i++) {
            int idx = tid + 128 * i;
            int r = idx >> 4, kq = idx & 15;
            float4 w4 = *(const float4*)(W + (size_t)(cbase + r) * C_ + k0 + kq * 4);
            uint32_t lo = packbf2(w4.x, w4.y), hi = packbf2(w4.z, w4.w);
            uint32_t d = wt_b + r * WROW + kq * 8;
            asm volatile("st.shared.v2.b32 [%0], {%1, %2};" :: "r"(d), "r"(lo), "r"(hi));
        }
        {
            int n = tid;
#pragma unroll
            for (int kg = 0; kg < 16; kg++) {
                int k = k0 + kg * 4;
                float a0 = xb[(size_t)(k + 0) * N_ + n0 + n];
                float a1 = xb[(size_t)(k + 1) * N_ + n0 + n];
                float a2 = xb[(size_t)(k + 2) * N_ + n0 + n];
                float a3 = xb[(size_t)(k + 3) * N_ + n0 + n];
                uint32_t lo = packbf2(a0, a1), hi = packbf2(a2, a3);
                uint32_t d = xt_b + n * XROW + kg * 8;
                asm volatile("st.shared.v2.b32 [%0], {%1, %2};" :: "r"(d), "r"(lo), "r"(hi));
            }
        }
        __syncthreads();

#pragma unroll
        for (int q = 0; q < 4; q++) {
            uint32_t af[2][4];
#pragma unroll
            for (int t = 0; t < 2; t++)
                ldsm4(af[t], waddr + t * 16 * WROW + q * 32);
#pragma unroll
            for (int np = 0; np < 8; np++) {
                uint32_t xb4[4];
                ldsm4(xb4, xaddr + np * 16 * XROW + q * 32);
#pragma unroll
                for (int t = 0; t < 2; t++) {
                    mma16816(acc[t][2 * np],     af[t], xb4[0], xb4[1]);
                    mma16816(acc[t][2 * np + 1], af[t], xb4[2], xb4[3]);
                }
            }
        }
    }

    uint8_t* outb = g_v + (size_t)z * C_ * N_;
#pragma unroll
    for (int t = 0; t < 2; t++) {
        int c0 = cbase + wrow + t * 16 + (lane >> 2);
#pragma unroll
        for (int nt = 0; nt < 16; nt++) {
            int n = n0 + nt * 8 + 2 * (lane & 3);
            *(uint16_t*)(outb + (size_t)c0 * N_ + n)       = pack2_e4m3(acc[t][nt][0], acc[t][nt][1]);
            *(uint16_t*)(outb + (size_t)(c0 + 8) * N_ + n) = pack2_e4m3(acc[t][nt][2], acc[t][nt][3]);
        }
    }
}

// ---------------------------------------------------------------------------
// final: out[b][o][n] = bf[o] + sum_c (gamma*Wf[o][c])*acc + Wf[o][C+c]*xf
__global__ void __launch_bounds__(128) final_kernel(const float* __restrict__ xf,
                                                    const float* __restrict__ Wf,
                                                    const float* __restrict__ bf,
                                                    const float* __restrict__ gptr,
                                                    float* __restrict__ out) {
    __shared__ float Wa[256 * 16], Wx[256 * 16];
    int tid = threadIdx.x;
    int b = blockIdx.z;
    int obase = blockIdx.y * 16;
    float gamma = gptr[0];
    for (int idx = tid; idx < 4096; idx += 128) {
        int c = idx >> 4, o = idx & 15;
        Wa[idx] = Wf[(size_t)(obase + o) * 512 + c] * gamma;
        Wx[idx] = Wf[(size_t)(obase + o) * 512 + 256 + c];
    }
    __syncthreads();
    int n = blockIdx.x * 512 + tid;
    const float* xb = xf + (size_t)b * C_ * N_;
    const float* ab = g_acc + (size_t)b * C_ * N_;
    float acc[4][16];
#pragma unroll
    for (int o = 0; o < 16; o++) {
        float bv = bf[obase + o];
#pragma unroll
        for (int q = 0; q < 4; q++) acc[q][o] = bv;
    }
    for (int c = 0; c < C_; c++) {
        float av[4], xv[4];
#pragma unroll
        for (int q = 0; q < 4; q++) {
            av[q] = ab[(size_t)c * N_ + n + 128 * q];
            xv[q] = xb[(size_t)c * N_ + n + 128 * q];
        }
        const float4* wa4 = (const float4*)(Wa + c * 16);
        const float4* wx4 = (const float4*)(Wx + c * 16);
#pragma unroll
        for (int g = 0; g < 4; g++) {
            float4 wa = wa4[g], wx = wx4[g];
#pragma unroll
            for (int q = 0; q < 4; q++) {
                acc[q][g * 4 + 0] = fmaf(wa.x, av[q], acc[q][g * 4 + 0]);
                acc[q][g * 4 + 0] = fmaf(wx.x, xv[q], acc[q][g * 4 + 0]);
                acc[q][g * 4 + 1] = fmaf(wa.y, av[q], acc[q][g * 4 + 1]);
                acc[q][g * 4 + 1] = fmaf(wx.y, xv[q], acc[q][g * 4 + 1]);
                acc[q][g * 4 + 2] = fmaf(wa.z, av[q], acc[q][g * 4 + 2]);
                acc[q][g * 4 + 2] = fmaf(wx.z, xv[q], acc[q][g * 4 + 2]);
                acc[q][g * 4 + 3] = fmaf(wa.w, av[q], acc[q][g * 4 + 3]);
                acc[q][g * 4 + 3] = fmaf(wx.w, xv[q], acc[q][g * 4 + 3]);
            }
        }
    }
#pragma unroll
    for (int o = 0; o < 16; o++) {
        float* p = out + ((size_t)b * C_ + obase + o) * N_ + n;
#pragma unroll
        for (int q = 0; q < 4; q++) p[128 * q] = acc[q][o];
    }
}

// ---------------------------------------------------------------------------
extern "C" void kernel_launch(void* const* d_in, const int* in_sizes, int n_in,
                              void* d_out, int out_size) {
    const float* x_f = (const float*)d_in[0];
    const float* x_b = (const float*)d_in[1];
    const float* Wq  = (const float*)d_in[2];
    const float* bq  = (const float*)d_in[3];
    const float* Wk  = (const float*)d_in[4];
    const float* bk  = (const float*)d_in[5];
    const float* Wv  = (const float*)d_in[6];
    const float* bv  = (const float*)d_in[7];
    const float* Wf  = (const float*)d_in[8];
    const float* bf  = (const float*)d_in[9];
    const float* gm  = (const float*)d_in[10];
    float* out = (float*)d_out;

    cudaFuncSetAttribute(attn_kernel, cudaFuncAttributeMaxDynamicSharedMemorySize, SM_TOTAL);

    proj_qk_kernel<<<dim3(N_ / 128, 1, B_), 128>>>(x_f, Wk, bk, 1);
    proj_qk_kernel<<<dim3(N_ / 128, 1, K_ * B_), 128>>>(x_b, Wq, bq, 0);
    proj_v_kernel<<<dim3(N_ / 128, C_ / 128, K_ * B_), 128>>>(x_b, Wv, bv);
    attn_kernel<<<dim3(N_ / TI, C_ / TC, B_), 128, SM_TOTAL>>>();
    final_kernel<<<dim3(N_ / 512, C_ / 16, B_), 128>>>(x_f, Wf, bf, gm, out);
}

// round 12
// speedup vs baseline: 1.2029x; 1.2029x over previous
#include <cuda_runtime.h>
#include <cuda_bf16.h>
#include <cstdint>
#include <math.h>

constexpr int B_  = 4;
constexpr int C_  = 256;
constexpr int C8_ = 32;
constexpr int N_  = 4096;
constexpr int K_  = 3;

constexpr int TI = 64;    // queries per CTA
constexpr int TJ = 64;    // keys per j-step
constexpr int NSTEP = N_ / TJ;

// ---- scratch (device globals; no allocation allowed) ----------------------
__device__ __nv_bfloat16 g_q[(size_t)K_ * B_ * N_ * C8_];   // [kk*B+b][n][o]
__device__ __nv_bfloat16 g_k[(size_t)B_ * N_ * C8_];        // [b][n][o]
__device__ __nv_bfloat16 g_v[(size_t)K_ * B_ * C_ * N_];    // [kk*B+b][c][n]
__device__ float         g_acc[(size_t)B_ * C_ * N_];       // [b][c][n]

// ---- helpers --------------------------------------------------------------
__device__ __forceinline__ uint32_t smem_u32(const void* p) {
    uint32_t a;
    asm("{ .reg .u64 t; cvta.to.shared.u64 t, %1; cvt.u32.u64 %0, t; }" : "=r"(a) : "l"(p));
    return a;
}
__device__ __forceinline__ void ldsm4(uint32_t* r, uint32_t addr) {
    asm volatile("ldmatrix.sync.aligned.m8n8.x4.shared.b16 {%0,%1,%2,%3}, [%4];"
                 : "=r"(r[0]), "=r"(r[1]), "=r"(r[2]), "=r"(r[3]) : "r"(addr));
}
__device__ __forceinline__ void mma16816(float* d, const uint32_t* a, uint32_t b0, uint32_t b1) {
    asm volatile("mma.sync.aligned.m16n8k16.row.col.f32.bf16.bf16.f32 "
                 "{%0,%1,%2,%3}, {%4,%5,%6,%7}, {%8,%9}, {%0,%1,%2,%3};"
                 : "+f"(d[0]), "+f"(d[1]), "+f"(d[2]), "+f"(d[3])
                 : "r"(a[0]), "r"(a[1]), "r"(a[2]), "r"(a[3]), "r"(b0), "r"(b1));
}
__device__ __forceinline__ uint32_t packbf2(float x, float y) {
    __nv_bfloat162 h = __float22bfloat162_rn(make_float2(x, y));
    return *(uint32_t*)&h;
}
__device__ __forceinline__ void cp16(uint32_t dst, const void* src) {
    asm volatile("cp.async.cg.shared.global [%0], [%1], 16;" :: "r"(dst), "l"(src));
}
#define CP_COMMIT() asm volatile("cp.async.commit_group;" ::: "memory")
#define CP_WAIT1()  asm volatile("cp.async.wait_group 1;" ::: "memory")

// ---- attn smem layout -----------------------------------------------------
constexpr int QROW = 80;    // 64B bf16 data + 16B pad
constexpr int KROW = 80;
constexpr int VROW = 144;   // 128B bf16 data + 16B pad
constexpr int SM_Q  = 0;                       // 64 * 80 = 5120
constexpr int SM_K0 = 5120;
constexpr int VOFF  = 64 * KROW;               // 5120
constexpr int BUFD  = VOFF + C_ * VROW;        // 5120 + 36864 = 41984
constexpr int SM_TOTAL = SM_K0 + 2 * BUFD;     // 89088

// ---------------------------------------------------------------------------
// attention: 128 threads, 4 warps, M=16 rows/warp, full C=256 channels.
// GEMM1 computed ONCE per (b, itile) — no channel-split duplication.
__global__ void __launch_bounds__(128, 2) attn_kernel() {
    extern __shared__ char smem[];
    uint32_t sb = smem_u32(smem);
    int tid = threadIdx.x, wid = tid >> 5, lane = tid & 31;
    int g = lane >> 2, m = lane & 3;
    int b = blockIdx.y;
    int itile = blockIdx.x * TI;
    int wrow = wid * 16;

    uint32_t qaddr = sb + SM_Q + (wrow + (lane & 15)) * QROW + ((lane >> 4) & 1) * 16;
    uint32_t koff = ((lane >> 4) * 8 + (lane & 7)) * KROW + ((lane >> 3) & 1) * 16;
    uint32_t voff = VOFF + ((lane >> 4) * 8 + (lane & 7)) * VROW + ((lane >> 3) & 1) * 16;

    const __nv_bfloat16* kbase = g_k + (size_t)b * N_ * C8_;

    for (int kk = 0; kk < K_; kk++) {
        size_t zb = (size_t)kk * B_ + b;
        const __nv_bfloat16* vbase = g_v + zb * (size_t)C_ * N_;
        __syncthreads();
        // Q tile -> smem (64 rows x 64B)
        const __nv_bfloat16* qp = g_q + (zb * N_ + itile) * C8_;
        for (int t = tid; t < 256; t += 128) {
            int r = t >> 2, ch = t & 3;
            *(uint4*)(smem + SM_Q + r * QROW + ch * 16) = *(const uint4*)(qp + r * C8_ + ch * 8);
        }

        // prologue: async-load K,V tile 0 into buffer 0
        {
            uint32_t bufb = sb + SM_K0;
#pragma unroll
            for (int i = 0; i < 2; i++) {
                int t = tid + 128 * i;
                int r = t >> 2, ch = t & 3;
                cp16(bufb + r * KROW + ch * 16, kbase + (size_t)r * C8_ + ch * 8);
            }
#pragma unroll
            for (int i = 0; i < 16; i++) {
                int t = tid + 128 * i;
                int c = t >> 3, ch = t & 7;
                cp16(bufb + VOFF + c * VROW + ch * 16, vbase + (size_t)c * N_ + ch * 8);
            }
            CP_COMMIT();
        }

        __syncthreads();
        uint32_t qa[2][4];
        ldsm4(qa[0], qaddr);
        ldsm4(qa[1], qaddr + 32);

        float Dn[32][4];
#pragma unroll
        for (int c = 0; c < 32; c++)
#pragma unroll
            for (int p = 0; p < 4; p++) Dn[c][p] = 0.f;
        float den0 = 0.f, den1 = 0.f;

        for (int js = 0; js < NSTEP; js++) {
            uint32_t bufb = sb + SM_K0 + (js & 1) * BUFD;
            if (js + 1 < NSTEP) {
                int jt2 = (js + 1) * TJ;
                uint32_t nb = sb + SM_K0 + ((js + 1) & 1) * BUFD;
#pragma unroll
                for (int i = 0; i < 2; i++) {
                    int t = tid + 128 * i;
                    int r = t >> 2, ch = t & 3;
                    cp16(nb + r * KROW + ch * 16, kbase + (size_t)(jt2 + r) * C8_ + ch * 8);
                }
#pragma unroll
                for (int i = 0; i < 16; i++) {
                    int t = tid + 128 * i;
                    int c = t >> 3, ch = t & 7;
                    cp16(nb + VOFF + c * VROW + ch * 16, vbase + (size_t)c * N_ + jt2 + ch * 8);
                }
            }
            CP_COMMIT();
            CP_WAIT1();
            __syncthreads();

            // ---- GEMM1 (bf16): S[16 x 64] = Q . K^T ----
            float s[8][4];
#pragma unroll
            for (int j = 0; j < 8; j++)
#pragma unroll
                for (int p = 0; p < 4; p++) s[j][p] = 0.f;
#pragma unroll
            for (int kc = 0; kc < 2; kc++) {
#pragma unroll
                for (int jp = 0; jp < 4; jp++) {
                    uint32_t kb[4];
                    ldsm4(kb, bufb + koff + jp * 16 * KROW + kc * 32);
                    mma16816(s[2 * jp],     qa[kc], kb[0], kb[1]);
                    mma16816(s[2 * jp + 1], qa[kc], kb[2], kb[3]);
                }
            }
            // ---- exp + pack, accumulate denominators ----
            uint32_t pa[8], pb[8];
#pragma unroll
            for (int j = 0; j < 8; j++) {
                float e0 = __expf(s[j][0]), e1 = __expf(s[j][1]);
                float e2 = __expf(s[j][2]), e3 = __expf(s[j][3]);
                den0 += e0 + e1;
                den1 += e2 + e3;
                pa[j] = packbf2(e0, e1);
                pb[j] = packbf2(e2, e3);
            }
            // ---- GEMM2 (bf16): D[16 x 256] += P . V^T ----
#pragma unroll
            for (int tp = 0; tp < 4; tp++) {
                uint32_t af[4] = {pa[2 * tp], pb[2 * tp], pa[2 * tp + 1], pb[2 * tp + 1]};
#pragma unroll
                for (int vp = 0; vp < 16; vp++) {
                    uint32_t vb[4];
                    ldsm4(vb, bufb + voff + vp * 16 * VROW + tp * 32);
                    mma16816(Dn[2 * vp],     af, vb[0], vb[1]);
                    mma16816(Dn[2 * vp + 1], af, vb[2], vb[3]);
                }
            }
            __syncthreads();
        }

        // denominators: reduce over the 4 lanes of each row
        den0 += __shfl_xor_sync(0xffffffffu, den0, 1);
        den0 += __shfl_xor_sync(0xffffffffu, den0, 2);
        den1 += __shfl_xor_sync(0xffffffffu, den1, 1);
        den1 += __shfl_xor_sync(0xffffffffu, den1, 2);
        float inv0 = 1.f / den0, inv1 = 1.f / den1;

        // normalize + accumulate into g_acc[b][c][n]
        float* accb = g_acc + (size_t)b * C_ * N_;
        int n0 = itile + wrow + g;
#pragma unroll
        for (int ct = 0; ct < 32; ct++) {
            int c = 8 * ct + 2 * m;
            float* p0 = accb + (size_t)c * N_ + n0;
            float* p1 = p0 + N_;
            float v0 = Dn[ct][0] * inv0, v1 = Dn[ct][1] * inv0;
            float v2 = Dn[ct][2] * inv1, v3 = Dn[ct][3] * inv1;
            if (kk == 0) {
                p0[0] = v0; p1[0] = v1; p0[8] = v2; p1[8] = v3;
            } else {
                p0[0] += v0; p1[0] += v1; p0[8] += v2; p1[8] += v3;
            }
        }
    }
}

// ---------------------------------------------------------------------------
// q/k projection via bf16 tensor cores: out[z][n][o] (o=32) = x^T.W^T + b
constexpr int PXROW = 144;
constexpr int PWROW = 144;

__global__ void __launch_bounds__(128, 4) proj_qk_kernel(const float* __restrict__ x,
                                                         const float* __restrict__ W,
                                                         const float* __restrict__ bias,
                                                         int which) {
    __shared__ char sm[128 * PXROW + 32 * PWROW];
    uint32_t xt_b = smem_u32(sm);
    uint32_t wt_b = xt_b + 128 * PXROW;
    int tid = threadIdx.x, wid = tid >> 5, lane = tid & 31;
    int z = blockIdx.z;
    int n0 = blockIdx.x * 128;
    int wrow = wid * 32;
    const float* xb = x + (size_t)z * C_ * N_;

    uint32_t xaddr = xt_b + (wrow + (lane & 15)) * PXROW + ((lane >> 4) & 1) * 16;
    uint32_t waddr = wt_b + ((lane >> 4) * 8 + (lane & 7)) * PWROW + ((lane >> 3) & 1) * 16;

    float s[2][4][4];
#pragma unroll
    for (int t = 0; t < 2; t++)
#pragma unroll
        for (int j = 0; j < 4; j++) {
            int o = j * 8 + 2 * (lane & 3);
            float b0 = bias[o], b1 = bias[o + 1];
            s[t][j][0] = b0; s[t][j][1] = b1;
            s[t][j][2] = b0; s[t][j][3] = b1;
        }

    for (int ks = 0; ks < 4; ks++) {
        int k0 = ks * 64;
        __syncthreads();
        {
            int n = tid;
#pragma unroll
            for (int kg = 0; kg < 16; kg++) {
                int k = k0 + kg * 4;
                float a0 = xb[(size_t)(k + 0) * N_ + n0 + n];
                float a1 = xb[(size_t)(k + 1) * N_ + n0 + n];
                float a2 = xb[(size_t)(k + 2) * N_ + n0 + n];
                float a3 = xb[(size_t)(k + 3) * N_ + n0 + n];
                uint32_t lo = packbf2(a0, a1), hi = packbf2(a2, a3);
                uint32_t d = xt_b + n * PXROW + kg * 8;
                asm volatile("st.shared.v2.b32 [%0], {%1, %2};" :: "r"(d), "r"(lo), "r"(hi));
            }
        }
#pragma unroll
        for (int i = 0; i < 4; i++) {
            int e = tid + 128 * i;
            int r = e >> 4, kq = e & 15;
            float4 w4 = *(const float4*)(W + (size_t)r * C_ + k0 + kq * 4);
            uint32_t lo = packbf2(w4.x, w4.y), hi = packbf2(w4.z, w4.w);
            uint32_t d = wt_b + r * PWROW + kq * 8;
            asm volatile("st.shared.v2.b32 [%0], {%1, %2};" :: "r"(d), "r"(lo), "r"(hi));
        }
        __syncthreads();

#pragma unroll
        for (int kc = 0; kc < 4; kc++) {
            uint32_t qa[2][4];
#pragma unroll
            for (int t = 0; t < 2; t++)
                ldsm4(qa[t], xaddr + t * 16 * PXROW + kc * 32);
#pragma unroll
            for (int jp = 0; jp < 2; jp++) {
                uint32_t wb[4];
                ldsm4(wb, waddr + jp * 16 * PWROW + kc * 32);
#pragma unroll
                for (int t = 0; t < 2; t++) {
                    mma16816(s[t][2 * jp],     qa[t], wb[0], wb[1]);
                    mma16816(s[t][2 * jp + 1], qa[t], wb[2], wb[3]);
                }
            }
        }
    }

    __nv_bfloat16* dst = (which ? g_k : g_q) + ((size_t)z * N_ + n0) * C8_;
#pragma unroll
    for (int t = 0; t < 2; t++) {
        int n = wrow + t * 16 + (lane >> 2);
#pragma unroll
        for (int j = 0; j < 4; j++) {
            int o = j * 8 + 2 * (lane & 3);
            *(uint32_t*)(dst + (size_t)n * C8_ + o)       = packbf2(s[t][j][0], s[t][j][1]);
            *(uint32_t*)(dst + (size_t)(n + 8) * C8_ + o) = packbf2(s[t][j][2], s[t][j][3]);
        }
    }
}

// ---------------------------------------------------------------------------
// v projection via bf16 tensor cores: g_v[z][c][n] = Wv[c][:].x[:][n] + bv[c]
constexpr int WROW = 144;
constexpr int XROW = 144;

__global__ void __launch_bounds__(128, 2) proj_v_kernel(const float* __restrict__ xball,
                                                        const float* __restrict__ W,
                                                        const float* __restrict__ bias) {
    __shared__ char sm[128 * WROW + 128 * XROW];
    uint32_t wt_b = smem_u32(sm);
    uint32_t xt_b = wt_b + 128 * WROW;
    int tid = threadIdx.x, wid = tid >> 5, lane = tid & 31;
    int z = blockIdx.z;
    int cbase = blockIdx.y * 128;
    int n0 = blockIdx.x * 128;
    int wrow = wid * 32;
    const float* xb = xball + (size_t)z * C_ * N_;

    uint32_t waddr = wt_b + (wrow + (lane & 15)) * WROW + ((lane >> 4) & 1) * 16;
    uint32_t xaddr = xt_b + ((lane >> 4) * 8 + (lane & 7)) * XROW + ((lane >> 3) & 1) * 16;

    float acc[2][16][4];
#pragma unroll
    for (int t = 0; t < 2; t++) {
        float b0 = bias[cbase + wrow + t * 16 + (lane >> 2)];
        float b1 = bias[cbase + wrow + t * 16 + (lane >> 2) + 8];
#pragma unroll
        for (int nt = 0; nt < 16; nt++) {
            acc[t][nt][0] = b0; acc[t][nt][1] = b0;
            acc[t][nt][2] = b1; acc[t][nt][3] = b1;
        }
    }

    for (int ks = 0; ks < 4; ks++) {
        int k0 = ks * 64;
        __syncthreads();
#pragma unroll
        for (int i = 0; i < 16; i++) {
            int idx = tid + 128 * i;
            int r = idx >> 4, kq = idx & 15;
            float4 w4 = *(const float4*)(W + (size_t)(cbase + r) * C_ + k0 + kq * 4);
            uint32_t lo = packbf2(w4.x, w4.y), hi = packbf2(w4.z, w4.w);
            uint32_t d = wt_b + r * WROW + kq * 8;
            asm volatile("st.shared.v2.b32 [%0], {%1, %2};" :: "r"(d), "r"(lo), "r"(hi));
        }
        {
            int n = tid;
#pragma unroll
            for (int kg = 0; kg < 16; kg++) {
                int k = k0 + kg * 4;
                float a0 = xb[(size_t)(k + 0) * N_ + n0 + n];
                float a1 = xb[(size_t)(k + 1) * N_ + n0 + n];
                float a2 = xb[(size_t)(k + 2) * N_ + n0 + n];
                float a3 = xb[(size_t)(k + 3) * N_ + n0 + n];
                uint32_t lo = packbf2(a0, a1), hi = packbf2(a2, a3);
                uint32_t d = xt_b + n * XROW + kg * 8;
                asm volatile("st.shared.v2.b32 [%0], {%1, %2};" :: "r"(d), "r"(lo), "r"(hi));
            }
        }
        __syncthreads();

#pragma unroll
        for (int q = 0; q < 4; q++) {
            uint32_t af[2][4];
#pragma unroll
            for (int t = 0; t < 2; t++)
                ldsm4(af[t], waddr + t * 16 * WROW + q * 32);
#pragma unroll
            for (int np = 0; np < 8; np++) {
                uint32_t xb4[4];
                ldsm4(xb4, xaddr + np * 16 * XROW + q * 32);
#pragma unroll
                for (int t = 0; t < 2; t++) {
                    mma16816(acc[t][2 * np],     af[t], xb4[0], xb4[1]);
                    mma16816(acc[t][2 * np + 1], af[t], xb4[2], xb4[3]);
                }
            }
        }
    }

    __nv_bfloat16* outb = g_v + (size_t)z * C_ * N_;
#pragma unroll
    for (int t = 0; t < 2; t++) {
        int c0 = cbase + wrow + t * 16 + (lane >> 2);
#pragma unroll
        for (int nt = 0; nt < 16; nt++) {
            int n = n0 + nt * 8 + 2 * (lane & 3);
            uint32_t lo = packbf2(acc[t][nt][0], acc[t][nt][1]);
            uint32_t hi = packbf2(acc[t][nt][2], acc[t][nt][3]);
            *(uint32_t*)(outb + (size_t)c0 * N_ + n) = lo;
            *(uint32_t*)(outb + (size_t)(c0 + 8) * N_ + n) = hi;
        }
    }
}

// ---------------------------------------------------------------------------
// final via error-compensated bf16 split GEMM over virtual k=1024:
//   block0: Wacc(bf16) . (gamma*acc)(bf16)
//   block1: Whi . xhi     block2: Whi . xlo     block3: Wlo . xhi
// dropped term Wlo.xlo ~ 2^-18 relative — negligible.
constexpr int FROW = 144;

__global__ void __launch_bounds__(128, 2) final_gemm(const float* __restrict__ xf,
                                                     const float* __restrict__ Wf,
                                                     const float* __restrict__ bfv,
                                                     const float* __restrict__ gptr,
                                                     float* __restrict__ out) {
    __shared__ char sm[128 * FROW + 128 * FROW];
    uint32_t wt_b = smem_u32(sm);
    uint32_t xt_b = wt_b + 128 * FROW;
    int tid = threadIdx.x, wid = tid >> 5, lane = tid & 31;
    int g = lane >> 2, m = lane & 3;
    int b = blockIdx.z;
    int obase = blockIdx.y * 128;
    int n0 = blockIdx.x * 128;
    int wrow = wid * 32;
    float gamma = gptr[0];
    const float* xb = xf + (size_t)b * C_ * N_;
    const float* ab = g_acc + (size_t)b * C_ * N_;

    uint32_t waddr = wt_b + (wrow + (lane & 15)) * FROW + ((lane >> 4) & 1) * 16;
    uint32_t xaddr = xt_b + ((lane >> 4) * 8 + (lane & 7)) * FROW + ((lane >> 3) & 1) * 16;

    float acc[2][16][4];
#pragma unroll
    for (int t = 0; t < 2; t++) {
        float b0 = bfv[obase + wrow + t * 16 + g];
        float b1 = bfv[obase + wrow + t * 16 + g + 8];
#pragma unroll
        for (int nt = 0; nt < 16; nt++) {
            acc[t][nt][0] = b0; acc[t][nt][1] = b0;
            acc[t][nt][2] = b1; acc[t][nt][3] = b1;
        }
    }

    for (int ks = 0; ks < 16; ks++) {
        int bs = ks >> 2;             // 0: acc, 1: Whi.xhi, 2: Whi.xlo, 3: Wlo.xhi
        int c64 = (ks & 3) * 64;
        __syncthreads();
        // W tile [128 o][64 k] with per-block transform
#pragma unroll
        for (int i = 0; i < 16; i++) {
            int idx = tid + 128 * i;
            int r = idx >> 4, kq = idx & 15;
            int c = c64 + kq * 4;
            const float* wp = Wf + (size_t)(obase + r) * 512 + (bs == 0 ? c : 256 + c);
            float4 w4 = *(const float4*)wp;
            uint32_t lo, hi;
            if (bs == 3) {
                float h0 = __bfloat162float(__float2bfloat16(w4.x));
                float h1 = __bfloat162float(__float2bfloat16(w4.y));
                float h2 = __bfloat162float(__float2bfloat16(w4.z));
                float h3 = __bfloat162float(__float2bfloat16(w4.w));
                lo = packbf2(w4.x - h0, w4.y - h1);
                hi = packbf2(w4.z - h2, w4.w - h3);
            } else {
                lo = packbf2(w4.x, w4.y);
                hi = packbf2(w4.z, w4.w);
            }
            uint32_t d = wt_b + r * FROW + kq * 8;
            asm volatile("st.shared.v2.b32 [%0], {%1, %2};" :: "r"(d), "r"(lo), "r"(hi));
        }
        // X tile [128 n][64 k] (transposed load + per-block transform)
        {
            int n = tid;
#pragma unroll
            for (int kg = 0; kg < 16; kg++) {
                int c = c64 + kg * 4;
                float a[4];
#pragma unroll
                for (int j = 0; j < 4; j++) {
                    if (bs == 0) {
                        a[j] = gamma * ab[(size_t)(c + j) * N_ + n0 + n];
                    } else {
                        float x = xb[(size_t)(c + j) * N_ + n0 + n];
                        if (bs == 2) {
                            float h = __bfloat162float(__float2bfloat16(x));
                            a[j] = x - h;
                        } else {
                            a[j] = x;   // packbf2 rounds -> xhi
                        }
                    }
                }
                uint32_t lo = packbf2(a[0], a[1]), hi = packbf2(a[2], a[3]);
                uint32_t d = xt_b + n * FROW + kg * 8;
                asm volatile("st.shared.v2.b32 [%0], {%1, %2};" :: "r"(d), "r"(lo), "r"(hi));
            }
        }
        __syncthreads();

#pragma unroll
        for (int kc = 0; kc < 4; kc++) {
            uint32_t af[2][4];
#pragma unroll
            for (int t = 0; t < 2; t++)
                ldsm4(af[t], waddr + t * 16 * FROW + kc * 32);
#pragma unroll
            for (int np = 0; np < 8; np++) {
                uint32_t xb4[4];
                ldsm4(xb4, xaddr + np * 16 * FROW + kc * 32);
#pragma unroll
                for (int t = 0; t < 2; t++) {
                    mma16816(acc[t][2 * np],     af[t], xb4[0], xb4[1]);
                    mma16816(acc[t][2 * np + 1], af[t], xb4[2], xb4[3]);
                }
            }
        }
    }

    // writeback fp32
#pragma unroll
    for (int t = 0; t < 2; t++) {
        int o0 = obase + wrow + t * 16 + g;
#pragma unroll
        for (int nt = 0; nt < 16; nt++) {
            int n = n0 + nt * 8 + 2 * m;
            float* p = out + ((size_t)b * C_ + o0) * N_ + n;
            float* q = p + 8 * N_;
            p[0] = acc[t][nt][0]; p[1] = acc[t][nt][1];
            q[0] = acc[t][nt][2]; q[1] = acc[t][nt][3];
        }
    }
}

// ---------------------------------------------------------------------------
extern "C" void kernel_launch(void* const* d_in, const int* in_sizes, int n_in,
                              void* d_out, int out_size) {
    const float* x_f = (const float*)d_in[0];
    const float* x_b = (const float*)d_in[1];
    const float* Wq  = (const float*)d_in[2];
    const float* bq  = (const float*)d_in[3];
    const float* Wk  = (const float*)d_in[4];
    const float* bk  = (const float*)d_in[5];
    const float* Wv  = (const float*)d_in[6];
    const float* bv  = (const float*)d_in[7];
    const float* Wf  = (const float*)d_in[8];
    const float* bf  = (const float*)d_in[9];
    const float* gm  = (const float*)d_in[10];
    float* out = (float*)d_out;

    cudaFuncSetAttribute(attn_kernel, cudaFuncAttributeMaxDynamicSharedMemorySize, SM_TOTAL);

    proj_qk_kernel<<<dim3(N_ / 128, 1, B_), 128>>>(x_f, Wk, bk, 1);
    proj_qk_kernel<<<dim3(N_ / 128, 1, K_ * B_), 128>>>(x_b, Wq, bq, 0);
    proj_v_kernel<<<dim3(N_ / 128, C_ / 128, K_ * B_), 128>>>(x_b, Wv, bv);
    attn_kernel<<<dim3(N_ / TI, B_), 128, SM_TOTAL>>>();
    final_gemm<<<dim3(N_ / 128, C_ / 128, B_), 128>>>(x_f, Wf, bf, gm, out);
}

// round 14
// speedup vs baseline: 1.2202x; 1.0144x over previous
#include <cuda_runtime.h>
#include <cuda_bf16.h>
#include <cstdint>
#include <math.h>

constexpr int B_  = 4;
constexpr int C_  = 256;
constexpr int C8_ = 32;
constexpr int N_  = 4096;
constexpr int K_  = 3;

constexpr int TI = 64;    // queries per CTA
constexpr int TJ = 64;    // keys per j-step
constexpr int NSTEP = N_ / TJ;

// ---- scratch (device globals; no allocation allowed) ----------------------
__device__ __nv_bfloat16 g_q[(size_t)K_ * B_ * N_ * C8_];   // [zb][n][o]
__device__ __nv_bfloat16 g_k[(size_t)B_ * N_ * C8_];        // [b][n][o]
__device__ __nv_bfloat16 g_v[(size_t)K_ * B_ * C_ * N_];    // [zb][c][n]
__device__ float         g_acc[(size_t)K_ * B_ * C_ * N_];  // [zb][c][n] per-kk slabs

// ---- helpers --------------------------------------------------------------
__device__ __forceinline__ uint32_t smem_u32(const void* p) {
    uint32_t a;
    asm("{ .reg .u64 t; cvta.to.shared.u64 t, %1; cvt.u32.u64 %0, t; }" : "=r"(a) : "l"(p));
    return a;
}
__device__ __forceinline__ void ldsm4(uint32_t* r, uint32_t addr) {
    asm volatile("ldmatrix.sync.aligned.m8n8.x4.shared.b16 {%0,%1,%2,%3}, [%4];"
                 : "=r"(r[0]), "=r"(r[1]), "=r"(r[2]), "=r"(r[3]) : "r"(addr));
}
__device__ __forceinline__ void mma16816(float* d, const uint32_t* a, uint32_t b0, uint32_t b1) {
    asm volatile("mma.sync.aligned.m16n8k16.row.col.f32.bf16.bf16.f32 "
                 "{%0,%1,%2,%3}, {%4,%5,%6,%7}, {%8,%9}, {%0,%1,%2,%3};"
                 : "+f"(d[0]), "+f"(d[1]), "+f"(d[2]), "+f"(d[3])
                 : "r"(a[0]), "r"(a[1]), "r"(a[2]), "r"(a[3]), "r"(b0), "r"(b1));
}
__device__ __forceinline__ uint32_t packbf2(float x, float y) {
    __nv_bfloat162 h = __float22bfloat162_rn(make_float2(x, y));
    return *(uint32_t*)&h;
}
__device__ __forceinline__ void cp16(uint32_t dst, const void* src) {
    asm volatile("cp.async.cg.shared.global [%0], [%1], 16;" :: "r"(dst), "l"(src));
}
#define CP_COMMIT() asm volatile("cp.async.commit_group;" ::: "memory")
#define CP_WAIT1()  asm volatile("cp.async.wait_group 1;" ::: "memory")

// ---- attn smem layout -----------------------------------------------------
constexpr int QROW = 80;
constexpr int KROW = 80;
constexpr int VROW = 144;
constexpr int SM_Q  = 0;                       // 64 * 80 = 5120
constexpr int SM_K0 = 5120;
constexpr int VOFF  = 64 * KROW;
constexpr int BUFD  = VOFF + C_ * VROW;        // 41984
constexpr int SM_TOTAL = SM_K0 + 2 * BUFD;     // 89088

// ---------------------------------------------------------------------------
// attention: grid (N/64, K*B); one (zb, itile) unit per CTA; plain stores.
__global__ void __launch_bounds__(128, 2) attn_kernel() {
    extern __shared__ char smem[];
    uint32_t sb = smem_u32(smem);
    int tid = threadIdx.x, wid = tid >> 5, lane = tid & 31;
    int g = lane >> 2, m = lane & 3;
    int zb = blockIdx.y;
    int b = zb & 3;
    int itile = blockIdx.x * TI;
    int wrow = wid * 16;

    uint32_t qaddr = sb + SM_Q + (wrow + (lane & 15)) * QROW + ((lane >> 4) & 1) * 16;
    uint32_t koff = ((lane >> 4) * 8 + (lane & 7)) * KROW + ((lane >> 3) & 1) * 16;
    uint32_t voff = VOFF + ((lane >> 4) * 8 + (lane & 7)) * VROW + ((lane >> 3) & 1) * 16;

    const __nv_bfloat16* kbase = g_k + (size_t)b * N_ * C8_;
    const __nv_bfloat16* vbase = g_v + (size_t)zb * C_ * N_;

    // Q tile -> smem (64 rows x 64B)
    const __nv_bfloat16* qp = g_q + ((size_t)zb * N_ + itile) * C8_;
    for (int t = tid; t < 256; t += 128) {
        int r = t >> 2, ch = t & 3;
        *(uint4*)(smem + SM_Q + r * QROW + ch * 16) = *(const uint4*)(qp + r * C8_ + ch * 8);
    }

    // prologue: async-load K,V tile 0 into buffer 0
    {
        uint32_t bufb = sb + SM_K0;
#pragma unroll
        for (int i = 0; i < 2; i++) {
            int t = tid + 128 * i;
            int r = t >> 2, ch = t & 3;
            cp16(bufb + r * KROW + ch * 16, kbase + (size_t)r * C8_ + ch * 8);
        }
#pragma unroll
        for (int i = 0; i < 16; i++) {
            int t = tid + 128 * i;
            int c = t >> 3, ch = t & 7;
            cp16(bufb + VOFF + c * VROW + ch * 16, vbase + (size_t)c * N_ + ch * 8);
        }
        CP_COMMIT();
    }

    __syncthreads();
    uint32_t qa[2][4];
    ldsm4(qa[0], qaddr);
    ldsm4(qa[1], qaddr + 32);

    float Dn[32][4];
#pragma unroll
    for (int c = 0; c < 32; c++)
#pragma unroll
        for (int p = 0; p < 4; p++) Dn[c][p] = 0.f;
    float den0 = 0.f, den1 = 0.f;

    for (int js = 0; js < NSTEP; js++) {
        uint32_t bufb = sb + SM_K0 + (js & 1) * BUFD;
        if (js + 1 < NSTEP) {
            int jt2 = (js + 1) * TJ;
            uint32_t nb = sb + SM_K0 + ((js + 1) & 1) * BUFD;
#pragma unroll
            for (int i = 0; i < 2; i++) {
                int t = tid + 128 * i;
                int r = t >> 2, ch = t & 3;
                cp16(nb + r * KROW + ch * 16, kbase + (size_t)(jt2 + r) * C8_ + ch * 8);
            }
#pragma unroll
            for (int i = 0; i < 16; i++) {
                int t = tid + 128 * i;
                int c = t >> 3, ch = t & 7;
                cp16(nb + VOFF + c * VROW + ch * 16, vbase + (size_t)c * N_ + jt2 + ch * 8);
            }
        }
        CP_COMMIT();
        CP_WAIT1();
        __syncthreads();

        // ---- GEMM1 (bf16): S[16 x 64] = Q . K^T ----
        float s[8][4];
#pragma unroll
        for (int j = 0; j < 8; j++)
#pragma unroll
            for (int p = 0; p < 4; p++) s[j][p] = 0.f;
#pragma unroll
        for (int kc = 0; kc < 2; kc++) {
#pragma unroll
            for (int jp = 0; jp < 4; jp++) {
                uint32_t kb[4];
                ldsm4(kb, bufb + koff + jp * 16 * KROW + kc * 32);
                mma16816(s[2 * jp],     qa[kc], kb[0], kb[1]);
                mma16816(s[2 * jp + 1], qa[kc], kb[2], kb[3]);
            }
        }
        // ---- exp + pack, accumulate denominators ----
        uint32_t pa[8], pb[8];
#pragma unroll
        for (int j = 0; j < 8; j++) {
            float e0 = __expf(s[j][0]), e1 = __expf(s[j][1]);
            float e2 = __expf(s[j][2]), e3 = __expf(s[j][3]);
            den0 += e0 + e1;
            den1 += e2 + e3;
            pa[j] = packbf2(e0, e1);
            pb[j] = packbf2(e2, e3);
        }
        // ---- GEMM2 (bf16): D[16 x 256] += P . V^T ----
#pragma unroll
        for (int tp = 0; tp < 4; tp++) {
            uint32_t af[4] = {pa[2 * tp], pb[2 * tp], pa[2 * tp + 1], pb[2 * tp + 1]};
#pragma unroll
            for (int vp = 0; vp < 16; vp++) {
                uint32_t vb[4];
                ldsm4(vb, bufb + voff + vp * 16 * VROW + tp * 32);
                mma16816(Dn[2 * vp],     af, vb[0], vb[1]);
                mma16816(Dn[2 * vp + 1], af, vb[2], vb[3]);
            }
        }
        __syncthreads();
    }

    den0 += __shfl_xor_sync(0xffffffffu, den0, 1);
    den0 += __shfl_xor_sync(0xffffffffu, den0, 2);
    den1 += __shfl_xor_sync(0xffffffffu, den1, 1);
    den1 += __shfl_xor_sync(0xffffffffu, den1, 2);
    float inv0 = 1.f / den0, inv1 = 1.f / den1;

    // normalize + store into per-kk slab g_acc[zb][c][n] (disjoint — plain stores)
    float* accb = g_acc + (size_t)zb * C_ * N_;
    int n0 = itile + wrow + g;
#pragma unroll
    for (int ct = 0; ct < 32; ct++) {
        int c = 8 * ct + 2 * m;
        float* p0 = accb + (size_t)c * N_ + n0;
        float* p1 = p0 + N_;
        p0[0] = Dn[ct][0] * inv0;
        p1[0] = Dn[ct][1] * inv0;
        p0[8] = Dn[ct][2] * inv1;
        p1[8] = Dn[ct][3] * inv1;
    }
}

// ---------------------------------------------------------------------------
// fused projections: one xt transpose per (n0, z).
//  z in [0,12): x_b slab zb=z  -> q = Wq.x + bq (g_q[zb]) AND v = Wv.x + bv (g_v[zb])
//  z in [12,16): x_f slab b=z-12 -> k = Wk.x + bk (g_k[b]) only
constexpr int PROW2 = 144;
constexpr int SMP_WV = 0;                        // 256 * 144 = 36864
constexpr int SMP_WQ = 36864;                    // 32 * 144  = 4608
constexpr int SMP_XT = 41472;                    // 128 * 144 = 18432
constexpr int SMP_TOTAL = 59904;

__global__ void __launch_bounds__(256, 1) proj_all(const float* __restrict__ xball,
                                                   const float* __restrict__ xf,
                                                   const float* __restrict__ Wq,
                                                   const float* __restrict__ bq,
                                                   const float* __restrict__ Wk,
                                                   const float* __restrict__ bk,
                                                   const float* __restrict__ Wv,
                                                   const float* __restrict__ bv) {
    extern __shared__ char psm[];
    uint32_t wv_b = smem_u32(psm);
    uint32_t wq_b = wv_b + SMP_WQ - SMP_WV + SMP_WV;  // = base + 36864
    wq_b = wv_b + SMP_WQ;
    uint32_t xt_b = wv_b + SMP_XT;
    int tid = threadIdx.x, wid = tid >> 5, lane = tid & 31;
    int g = lane >> 2, m = lane & 3;
    int z = blockIdx.z;
    int n0 = blockIdx.x * 128;
    bool isK = (z >= K_ * B_);
    const float* xb = isK ? (xf + (size_t)(z - K_ * B_) * C_ * N_)
                          : (xball + (size_t)z * C_ * N_);
    const float* Wqk = isK ? Wk : Wq;
    const float* bqk = isK ? bk : bq;

    // v-phase addresses (8 warps x M=32 channels)
    int wrowv = wid * 32;
    uint32_t waddr = wv_b + (wrowv + (lane & 15)) * PROW2 + ((lane >> 4) & 1) * 16;
    uint32_t xaddrB = xt_b + ((lane >> 4) * 8 + (lane & 7)) * PROW2 + ((lane >> 3) & 1) * 16;
    // q-phase addresses (8 warps x M=16 n-rows; A = xt, B = Wqk)
    uint32_t xaddrA = xt_b + (wid * 16 + (lane & 15)) * PROW2 + ((lane >> 4) & 1) * 16;
    uint32_t qwaddr = wq_b + ((lane >> 4) * 8 + (lane & 7)) * PROW2 + ((lane >> 3) & 1) * 16;

    float accv[2][16][4];
    if (!isK) {
#pragma unroll
        for (int t = 0; t < 2; t++) {
            float b0 = bv[wrowv + t * 16 + g];
            float b1 = bv[wrowv + t * 16 + g + 8];
#pragma unroll
            for (int nt = 0; nt < 16; nt++) {
                accv[t][nt][0] = b0; accv[t][nt][1] = b0;
                accv[t][nt][2] = b1; accv[t][nt][3] = b1;
            }
        }
    }
    float accq[4][4];
#pragma unroll
    for (int j = 0; j < 4; j++) {
        int o = j * 8 + 2 * m;
        float b0 = bqk[o], b1 = bqk[o + 1];
        accq[j][0] = b0; accq[j][1] = b1;
        accq[j][2] = b0; accq[j][3] = b1;
    }

    for (int ks = 0; ks < 4; ks++) {
        int k0 = ks * 64;
        __syncthreads();
        // Wv tile [256 c][64 k] fp32 -> bf16 (only needed for !isK)
        if (!isK) {
#pragma unroll
            for (int i = 0; i < 16; i++) {
                int idx = tid + 256 * i;
                int r = idx >> 4, kq = idx & 15;
                float4 w4 = *(const float4*)(Wv + (size_t)r * C_ + k0 + kq * 4);
                uint32_t lo = packbf2(w4.x, w4.y), hi = packbf2(w4.z, w4.w);
                uint32_t d = wv_b + r * PROW2 + kq * 8;
                asm volatile("st.shared.v2.b32 [%0], {%1, %2};" :: "r"(d), "r"(lo), "r"(hi));
            }
        }
        // Wq/Wk tile [32 o][64 k]
#pragma unroll
        for (int i = 0; i < 2; i++) {
            int e = tid + 256 * i;
            int r = e >> 4, kq = e & 15;
            float4 w4 = *(const float4*)(Wqk + (size_t)r * C_ + k0 + kq * 4);
            uint32_t lo = packbf2(w4.x, w4.y), hi = packbf2(w4.z, w4.w);
            uint32_t d = wq_b + r * PROW2 + kq * 8;
            asm volatile("st.shared.v2.b32 [%0], {%1, %2};" :: "r"(d), "r"(lo), "r"(hi));
        }
        // xt tile [128 n][64 k] (transpose + convert) — threads split n/kg
        {
            int n = tid & 127;
            int kgbase = (tid >> 7) * 8;
#pragma unroll
            for (int kg2 = 0; kg2 < 8; kg2++) {
                int kg = kgbase + kg2;
                int k = k0 + kg * 4;
                float a0 = xb[(size_t)(k + 0) * N_ + n0 + n];
                float a1 = xb[(size_t)(k + 1) * N_ + n0 + n];
                float a2 = xb[(size_t)(k + 2) * N_ + n0 + n];
                float a3 = xb[(size_t)(k + 3) * N_ + n0 + n];
                uint32_t lo = packbf2(a0, a1), hi = packbf2(a2, a3);
                uint32_t d = xt_b + n * PROW2 + kg * 8;
                asm volatile("st.shared.v2.b32 [%0], {%1, %2};" :: "r"(d), "r"(lo), "r"(hi));
            }
        }
        __syncthreads();

#pragma unroll
        for (int kc = 0; kc < 4; kc++) {
            // q phase: A = xt (M=16 rows of n), B = Wqk (N=32)
            {
                uint32_t xa[4];
                ldsm4(xa, xaddrA + kc * 32);
                uint32_t wb0[4], wb1[4];
                ldsm4(wb0, qwaddr + kc * 32);
                ldsm4(wb1, qwaddr + 16 * PROW2 + kc * 32);
                mma16816(accq[0], xa, wb0[0], wb0[1]);
                mma16816(accq[1], xa, wb0[2], wb0[3]);
                mma16816(accq[2], xa, wb1[0], wb1[1]);
                mma16816(accq[3], xa, wb1[2], wb1[3]);
            }
            // v phase: A = Wv (M=32 channels/warp), B = xt (N=128)
            if (!isK) {
                uint32_t af[2][4];
#pragma unroll
                for (int t = 0; t < 2; t++)
                    ldsm4(af[t], waddr + t * 16 * PROW2 + kc * 32);
#pragma unroll
                for (int np = 0; np < 8; np++) {
                    uint32_t xb4[4];
                    ldsm4(xb4, xaddrB + np * 16 * PROW2 + kc * 32);
#pragma unroll
                    for (int t = 0; t < 2; t++) {
                        mma16816(accv[t][2 * np],     af[t], xb4[0], xb4[1]);
                        mma16816(accv[t][2 * np + 1], af[t], xb4[2], xb4[3]);
                    }
                }
            }
        }
    }

    // q/k writeback: [n][32] bf16, packed pairs (o, o+1)
    {
        __nv_bfloat16* dst = (isK ? g_k + (size_t)(z - K_ * B_) * N_ * C8_
                                  : g_q + (size_t)z * N_ * C8_) + (size_t)n0 * C8_;
        int n = wid * 16 + g;
#pragma unroll
        for (int j = 0; j < 4; j++) {
            int o = j * 8 + 2 * m;
            *(uint32_t*)(dst + (size_t)n * C8_ + o)       = packbf2(accq[j][0], accq[j][1]);
            *(uint32_t*)(dst + (size_t)(n + 8) * C8_ + o) = packbf2(accq[j][2], accq[j][3]);
        }
    }
    // v writeback: [c][n] bf16
    if (!isK) {
        __nv_bfloat16* outb = g_v + (size_t)z * C_ * N_;
#pragma unroll
        for (int t = 0; t < 2; t++) {
            int c0 = wrowv + t * 16 + g;
#pragma unroll
            for (int nt = 0; nt < 16; nt++) {
                int n = n0 + nt * 8 + 2 * m;
                *(uint32_t*)(outb + (size_t)c0 * N_ + n)       = packbf2(accv[t][nt][0], accv[t][nt][1]);
                *(uint32_t*)(outb + (size_t)(c0 + 8) * N_ + n) = packbf2(accv[t][nt][2], accv[t][nt][3]);
            }
        }
    }
}

// ---------------------------------------------------------------------------
// final via error-compensated bf16 split GEMM over virtual k=1024:
//   block0: Wacc . (gamma*(acc0+acc1+acc2))   block1: Whi.xhi
//   block2: Whi.xlo                           block3: Wlo.xhi
constexpr int FROW = 144;

__global__ void __launch_bounds__(128, 2) final_gemm(const float* __restrict__ xf,
                                                     const float* __restrict__ Wf,
                                                     const float* __restrict__ bfv,
                                                     const float* __restrict__ gptr,
                                                     float* __restrict__ out) {
    __shared__ char sm[128 * FROW + 128 * FROW];
    uint32_t wt_b = smem_u32(sm);
    uint32_t xt_b = wt_b + 128 * FROW;
    int tid = threadIdx.x, wid = tid >> 5, lane = tid & 31;
    int g = lane >> 2, m = lane & 3;
    int b = blockIdx.z;
    int obase = blockIdx.y * 128;
    int n0 = blockIdx.x * 128;
    int wrow = wid * 32;
    float gamma = gptr[0];
    const float* xb = xf + (size_t)b * C_ * N_;
    const float* ab0 = g_acc + (size_t)(0 * B_ + b) * C_ * N_;
    const float* ab1 = g_acc + (size_t)(1 * B_ + b) * C_ * N_;
    const float* ab2 = g_acc + (size_t)(2 * B_ + b) * C_ * N_;

    uint32_t waddr = wt_b + (wrow + (lane & 15)) * FROW + ((lane >> 4) & 1) * 16;
    uint32_t xaddr = xt_b + ((lane >> 4) * 8 + (lane & 7)) * FROW + ((lane >> 3) & 1) * 16;

    float acc[2][16][4];
#pragma unroll
    for (int t = 0; t < 2; t++) {
        float b0 = bfv[obase + wrow + t * 16 + g];
        float b1 = bfv[obase + wrow + t * 16 + g + 8];
#pragma unroll
        for (int nt = 0; nt < 16; nt++) {
            acc[t][nt][0] = b0; acc[t][nt][1] = b0;
            acc[t][nt][2] = b1; acc[t][nt][3] = b1;
        }
    }

    for (int ks = 0; ks < 16; ks++) {
        int bs = ks >> 2;
        int c64 = (ks & 3) * 64;
        __syncthreads();
#pragma unroll
        for (int i = 0; i < 16; i++) {
            int idx = tid + 128 * i;
            int r = idx >> 4, kq = idx & 15;
            int c = c64 + kq * 4;
            const float* wp = Wf + (size_t)(obase + r) * 512 + (bs == 0 ? c : 256 + c);
            float4 w4 = *(const float4*)wp;
            uint32_t lo, hi;
            if (bs == 3) {
                float h0 = __bfloat162float(__float2bfloat16(w4.x));
                float h1 = __bfloat162float(__float2bfloat16(w4.y));
                float h2 = __bfloat162float(__float2bfloat16(w4.z));
                float h3 = __bfloat162float(__float2bfloat16(w4.w));
                lo = packbf2(w4.x - h0, w4.y - h1);
                hi = packbf2(w4.z - h2, w4.w - h3);
            } else {
                lo = packbf2(w4.x, w4.y);
                hi = packbf2(w4.z, w4.w);
            }
            uint32_t d = wt_b + r * FROW + kq * 8;
            asm volatile("st.shared.v2.b32 [%0], {%1, %2};" :: "r"(d), "r"(lo), "r"(hi));
        }
        {
            int n = tid;
#pragma unroll
            for (int kg = 0; kg < 16; kg++) {
                int c = c64 + kg * 4;
                float a[4];
#pragma unroll
                for (int j = 0; j < 4; j++) {
                    size_t idx = (size_t)(c + j) * N_ + n0 + n;
                    if (bs == 0) {
                        a[j] = gamma * (ab0[idx] + ab1[idx] + ab2[idx]);
                    } else {
                        float x = xb[idx];
                        if (bs == 2) {
                            float h = __bfloat162float(__float2bfloat16(x));
                            a[j] = x - h;
                        } else {
                            a[j] = x;
                        }
                    }
                }
                uint32_t lo = packbf2(a[0], a[1]), hi = packbf2(a[2], a[3]);
                uint32_t d = xt_b + n * FROW + kg * 8;
                asm volatile("st.shared.v2.b32 [%0], {%1, %2};" :: "r"(d), "r"(lo), "r"(hi));
            }
        }
        __syncthreads();

#pragma unroll
        for (int kc = 0; kc < 4; kc++) {
            uint32_t af[2][4];
#pragma unroll
            for (int t = 0; t < 2; t++)
                ldsm4(af[t], waddr + t * 16 * FROW + kc * 32);
#pragma unroll
            for (int np = 0; np < 8; np++) {
                uint32_t xb4[4];
                ldsm4(xb4, xaddr + np * 16 * FROW + kc * 32);
#pragma unroll
                for (int t = 0; t < 2; t++) {
                    mma16816(acc[t][2 * np],     af[t], xb4[0], xb4[1]);
                    mma16816(acc[t][2 * np + 1], af[t], xb4[2], xb4[3]);
                }
            }
        }
    }

#pragma unroll
    for (int t = 0; t < 2; t++) {
        int o0 = obase + wrow + t * 16 + g;
#pragma unroll
        for (int nt = 0; nt < 16; nt++) {
            int n = n0 + nt * 8 + 2 * m;
            float* p = out + ((size_t)b * C_ + o0) * N_ + n;
            float* q = p + 8 * N_;
            p[0] = acc[t][nt][0]; p[1] = acc[t][nt][1];
            q[0] = acc[t][nt][2]; q[1] = acc[t][nt][3];
        }
    }
}

// ---------------------------------------------------------------------------
extern "C" void kernel_launch(void* const* d_in, const int* in_sizes, int n_in,
                              void* d_out, int out_size) {
    const float* x_f = (const float*)d_in[0];
    const float* x_b = (const float*)d_in[1];
    const float* Wq  = (const float*)d_in[2];
    const float* bq  = (const float*)d_in[3];
    const float* Wk  = (const float*)d_in[4];
    const float* bk  = (const float*)d_in[5];
    const float* Wv  = (const float*)d_in[6];
    const float* bv  = (const float*)d_in[7];
    const float* Wf  = (const float*)d_in[8];
    const float* bf  = (const float*)d_in[9];
    const float* gm  = (const float*)d_in[10];
    float* out = (float*)d_out;

    cudaFuncSetAttribute(attn_kernel, cudaFuncAttributeMaxDynamicSharedMemorySize, SM_TOTAL);
    cudaFuncSetAttribute(proj_all, cudaFuncAttributeMaxDynamicSharedMemorySize, SMP_TOTAL);

    proj_all<<<dim3(N_ / 128, 1, K_ * B_ + B_), 256, SMP_TOTAL>>>(x_b, x_f, Wq, bq, Wk, bk, Wv, bv);
    attn_kernel<<<dim3(N_ / TI, K_ * B_), 128, SM_TOTAL>>>();
    final_gemm<<<dim3(N_ / 128, C_ / 128, B_), 128>>>(x_f, Wf, bf, gm, out);
}

// round 15
// speedup vs baseline: 1.3855x; 1.1354x over previous
#include <cuda_runtime.h>
#include <cuda_bf16.h>
#include <cstdint>
#include <math.h>

constexpr int B_  = 4;
constexpr int C_  = 256;
constexpr int C8_ = 32;
constexpr int N_  = 4096;
constexpr int K_  = 3;

constexpr int TI = 64;    // queries per CTA
constexpr int TJ = 64;    // keys per j-step
constexpr int NSTEP = N_ / TJ;

// ---- scratch (device globals; no allocation allowed) ----------------------
__device__ __nv_bfloat16 g_q[(size_t)K_ * B_ * N_ * C8_];   // [zb][n][o]
__device__ __nv_bfloat16 g_k[(size_t)B_ * N_ * C8_];        // [b][n][o]
__device__ __nv_bfloat16 g_v[(size_t)K_ * B_ * C_ * N_];    // [zb][c][n]
__device__ float         g_acc[(size_t)K_ * B_ * C_ * N_];  // [zb][c][n] per-kk slabs
// final-path precomputed bf16 operands
__device__ __nv_bfloat16 g_wfa[256 * 256];                  // gamma * Wf[:, :256]
__device__ __nv_bfloat16 g_wfx_hi[256 * 256];               // hi(Wf[:, 256:])
__device__ __nv_bfloat16 g_wfx_lo[256 * 256];               // lo(Wf[:, 256:])
__device__ __nv_bfloat16 g_accb[(size_t)B_ * N_ * C_];      // [b][n][c] bf16(sum acc)
__device__ __nv_bfloat16 g_xhi [(size_t)B_ * N_ * C_];      // [b][n][c]
__device__ __nv_bfloat16 g_xlo [(size_t)B_ * N_ * C_];      // [b][n][c]

// ---- helpers --------------------------------------------------------------
__device__ __forceinline__ uint32_t smem_u32(const void* p) {
    uint32_t a;
    asm("{ .reg .u64 t; cvta.to.shared.u64 t, %1; cvt.u32.u64 %0, t; }" : "=r"(a) : "l"(p));
    return a;
}
__device__ __forceinline__ void ldsm4(uint32_t* r, uint32_t addr) {
    asm volatile("ldmatrix.sync.aligned.m8n8.x4.shared.b16 {%0,%1,%2,%3}, [%4];"
                 : "=r"(r[0]), "=r"(r[1]), "=r"(r[2]), "=r"(r[3]) : "r"(addr));
}
__device__ __forceinline__ void mma16816(float* d, const uint32_t* a, uint32_t b0, uint32_t b1) {
    asm volatile("mma.sync.aligned.m16n8k16.row.col.f32.bf16.bf16.f32 "
                 "{%0,%1,%2,%3}, {%4,%5,%6,%7}, {%8,%9}, {%0,%1,%2,%3};"
                 : "+f"(d[0]), "+f"(d[1]), "+f"(d[2]), "+f"(d[3])
                 : "r"(a[0]), "r"(a[1]), "r"(a[2]), "r"(a[3]), "r"(b0), "r"(b1));
}
__device__ __forceinline__ uint32_t packbf2(float x, float y) {
    __nv_bfloat162 h = __float22bfloat162_rn(make_float2(x, y));
    return *(uint32_t*)&h;
}
__device__ __forceinline__ void cp16(uint32_t dst, const void* src) {
    asm volatile("cp.async.cg.shared.global [%0], [%1], 16;" :: "r"(dst), "l"(src));
}
#define CP_COMMIT() asm volatile("cp.async.commit_group;" ::: "memory")
#define CP_WAIT1()  asm volatile("cp.async.wait_group 1;" ::: "memory")

// ---- attn smem layout -----------------------------------------------------
constexpr int QROW = 80;
constexpr int KROW = 80;
constexpr int VROW = 144;
constexpr int SM_Q  = 0;
constexpr int SM_K0 = 5120;
constexpr int VOFF  = 64 * KROW;
constexpr int BUFD  = VOFF + C_ * VROW;        // 41984
constexpr int SM_TOTAL = SM_K0 + 2 * BUFD;     // 89088

// ---------------------------------------------------------------------------
// attention: grid (N/64, K*B); one (zb, itile) unit per CTA; plain stores.
__global__ void __launch_bounds__(128, 2) attn_kernel() {
    extern __shared__ char smem[];
    uint32_t sb = smem_u32(smem);
    int tid = threadIdx.x, wid = tid >> 5, lane = tid & 31;
    int g = lane >> 2, m = lane & 3;
    int zb = blockIdx.y;
    int b = zb & 3;
    int itile = blockIdx.x * TI;
    int wrow = wid * 16;

    uint32_t qaddr = sb + SM_Q + (wrow + (lane & 15)) * QROW + ((lane >> 4) & 1) * 16;
    uint32_t koff = ((lane >> 4) * 8 + (lane & 7)) * KROW + ((lane >> 3) & 1) * 16;
    uint32_t voff = VOFF + ((lane >> 4) * 8 + (lane & 7)) * VROW + ((lane >> 3) & 1) * 16;

    const __nv_bfloat16* kbase = g_k + (size_t)b * N_ * C8_;
    const __nv_bfloat16* vbase = g_v + (size_t)zb * C_ * N_;

    const __nv_bfloat16* qp = g_q + ((size_t)zb * N_ + itile) * C8_;
    for (int t = tid; t < 256; t += 128) {
        int r = t >> 2, ch = t & 3;
        *(uint4*)(smem + SM_Q + r * QROW + ch * 16) = *(const uint4*)(qp + r * C8_ + ch * 8);
    }

    {
        uint32_t bufb = sb + SM_K0;
#pragma unroll
        for (int i = 0; i < 2; i++) {
            int t = tid + 128 * i;
            int r = t >> 2, ch = t & 3;
            cp16(bufb + r * KROW + ch * 16, kbase + (size_t)r * C8_ + ch * 8);
        }
#pragma unroll
        for (int i = 0; i < 16; i++) {
            int t = tid + 128 * i;
            int c = t >> 3, ch = t & 7;
            cp16(bufb + VOFF + c * VROW + ch * 16, vbase + (size_t)c * N_ + ch * 8);
        }
        CP_COMMIT();
    }

    __syncthreads();
    uint32_t qa[2][4];
    ldsm4(qa[0], qaddr);
    ldsm4(qa[1], qaddr + 32);

    float Dn[32][4];
#pragma unroll
    for (int c = 0; c < 32; c++)
#pragma unroll
        for (int p = 0; p < 4; p++) Dn[c][p] = 0.f;
    float den0 = 0.f, den1 = 0.f;

    for (int js = 0; js < NSTEP; js++) {
        uint32_t bufb = sb + SM_K0 + (js & 1) * BUFD;
        if (js + 1 < NSTEP) {
            int jt2 = (js + 1) * TJ;
            uint32_t nb = sb + SM_K0 + ((js + 1) & 1) * BUFD;
#pragma unroll
            for (int i = 0; i < 2; i++) {
                int t = tid + 128 * i;
                int r = t >> 2, ch = t & 3;
                cp16(nb + r * KROW + ch * 16, kbase + (size_t)(jt2 + r) * C8_ + ch * 8);
            }
#pragma unroll
            for (int i = 0; i < 16; i++) {
                int t = tid + 128 * i;
                int c = t >> 3, ch = t & 7;
                cp16(nb + VOFF + c * VROW + ch * 16, vbase + (size_t)c * N_ + jt2 + ch * 8);
            }
        }
        CP_COMMIT();
        CP_WAIT1();
        __syncthreads();

        // ---- GEMM1 (bf16): S[16 x 64] = Q . K^T ----
        float s[8][4];
#pragma unroll
        for (int j = 0; j < 8; j++)
#pragma unroll
            for (int p = 0; p < 4; p++) s[j][p] = 0.f;
#pragma unroll
        for (int kc = 0; kc < 2; kc++) {
#pragma unroll
            for (int jp = 0; jp < 4; jp++) {
                uint32_t kb[4];
                ldsm4(kb, bufb + koff + jp * 16 * KROW + kc * 32);
                mma16816(s[2 * jp],     qa[kc], kb[0], kb[1]);
                mma16816(s[2 * jp + 1], qa[kc], kb[2], kb[3]);
            }
        }
        // ---- exp + pack, accumulate denominators ----
        uint32_t pa[8], pb[8];
#pragma unroll
        for (int j = 0; j < 8; j++) {
            float e0 = __expf(s[j][0]), e1 = __expf(s[j][1]);
            float e2 = __expf(s[j][2]), e3 = __expf(s[j][3]);
            den0 += e0 + e1;
            den1 += e2 + e3;
            pa[j] = packbf2(e0, e1);
            pb[j] = packbf2(e2, e3);
        }
        // ---- GEMM2 (bf16): D[16 x 256] += P . V^T ----
#pragma unroll
        for (int tp = 0; tp < 4; tp++) {
            uint32_t af[4] = {pa[2 * tp], pb[2 * tp], pa[2 * tp + 1], pb[2 * tp + 1]};
#pragma unroll
            for (int vp = 0; vp < 16; vp++) {
                uint32_t vb[4];
                ldsm4(vb, bufb + voff + vp * 16 * VROW + tp * 32);
                mma16816(Dn[2 * vp],     af, vb[0], vb[1]);
                mma16816(Dn[2 * vp + 1], af, vb[2], vb[3]);
            }
        }
        __syncthreads();
    }

    den0 += __shfl_xor_sync(0xffffffffu, den0, 1);
    den0 += __shfl_xor_sync(0xffffffffu, den0, 2);
    den1 += __shfl_xor_sync(0xffffffffu, den1, 1);
    den1 += __shfl_xor_sync(0xffffffffu, den1, 2);
    float inv0 = 1.f / den0, inv1 = 1.f / den1;

    float* accb = g_acc + (size_t)zb * C_ * N_;
    int n0 = itile + wrow + g;
#pragma unroll
    for (int ct = 0; ct < 32; ct++) {
        int c = 8 * ct + 2 * m;
        float* p0 = accb + (size_t)c * N_ + n0;
        float* p1 = p0 + N_;
        p0[0] = Dn[ct][0] * inv0;
        p1[0] = Dn[ct][1] * inv0;
        p0[8] = Dn[ct][2] * inv1;
        p1[8] = Dn[ct][3] * inv1;
    }
}

// ---------------------------------------------------------------------------
// fused projections (unchanged from R14, dead code removed)
constexpr int PROW2 = 144;
constexpr int SMP_WQ = 36864;
constexpr int SMP_XT = 41472;
constexpr int SMP_TOTAL = 59904;

__global__ void __launch_bounds__(256, 1) proj_all(const float* __restrict__ xball,
                                                   const float* __restrict__ xf,
                                                   const float* __restrict__ Wq,
                                                   const float* __restrict__ bq,
                                                   const float* __restrict__ Wk,
                                                   const float* __restrict__ bk,
                                                   const float* __restrict__ Wv,
                                                   const float* __restrict__ bv) {
    extern __shared__ char psm[];
    uint32_t wv_b = smem_u32(psm);
    uint32_t wq_b = wv_b + SMP_WQ;
    uint32_t xt_b = wv_b + SMP_XT;
    int tid = threadIdx.x, wid = tid >> 5, lane = tid & 31;
    int g = lane >> 2, m = lane & 3;
    int z = blockIdx.z;
    int n0 = blockIdx.x * 128;
    bool isK = (z >= K_ * B_);
    const float* xb = isK ? (xf + (size_t)(z - K_ * B_) * C_ * N_)
                          : (xball + (size_t)z * C_ * N_);
    const float* Wqk = isK ? Wk : Wq;
    const float* bqk = isK ? bk : bq;

    int wrowv = wid * 32;
    uint32_t waddr = wv_b + (wrowv + (lane & 15)) * PROW2 + ((lane >> 4) & 1) * 16;
    uint32_t xaddrB = xt_b + ((lane >> 4) * 8 + (lane & 7)) * PROW2 + ((lane >> 3) & 1) * 16;
    uint32_t xaddrA = xt_b + (wid * 16 + (lane & 15)) * PROW2 + ((lane >> 4) & 1) * 16;
    uint32_t qwaddr = wq_b + ((lane >> 4) * 8 + (lane & 7)) * PROW2 + ((lane >> 3) & 1) * 16;

    float accv[2][16][4];
    if (!isK) {
#pragma unroll
        for (int t = 0; t < 2; t++) {
            float b0 = bv[wrowv + t * 16 + g];
            float b1 = bv[wrowv + t * 16 + g + 8];
#pragma unroll
            for (int nt = 0; nt < 16; nt++) {
                accv[t][nt][0] = b0; accv[t][nt][1] = b0;
                accv[t][nt][2] = b1; accv[t][nt][3] = b1;
            }
        }
    }
    float accq[4][4];
#pragma unroll
    for (int j = 0; j < 4; j++) {
        int o = j * 8 + 2 * m;
        float b0 = bqk[o], b1 = bqk[o + 1];
        accq[j][0] = b0; accq[j][1] = b1;
        accq[j][2] = b0; accq[j][3] = b1;
    }

    for (int ks = 0; ks < 4; ks++) {
        int k0 = ks * 64;
        __syncthreads();
        if (!isK) {
#pragma unroll
            for (int i = 0; i < 16; i++) {
                int idx = tid + 256 * i;
                int r = idx >> 4, kq = idx & 15;
                float4 w4 = *(const float4*)(Wv + (size_t)r * C_ + k0 + kq * 4);
                uint32_t lo = packbf2(w4.x, w4.y), hi = packbf2(w4.z, w4.w);
                uint32_t d = wv_b + r * PROW2 + kq * 8;
                asm volatile("st.shared.v2.b32 [%0], {%1, %2};" :: "r"(d), "r"(lo), "r"(hi));
            }
        }
#pragma unroll
        for (int i = 0; i < 2; i++) {
            int e = tid + 256 * i;
            int r = e >> 4, kq = e & 15;
            float4 w4 = *(const float4*)(Wqk + (size_t)r * C_ + k0 + kq * 4);
            uint32_t lo = packbf2(w4.x, w4.y), hi = packbf2(w4.z, w4.w);
            uint32_t d = wq_b + r * PROW2 + kq * 8;
            asm volatile("st.shared.v2.b32 [%0], {%1, %2};" :: "r"(d), "r"(lo), "r"(hi));
        }
        {
            int n = tid & 127;
            int kgbase = (tid >> 7) * 8;
#pragma unroll
            for (int kg2 = 0; kg2 < 8; kg2++) {
                int kg = kgbase + kg2;
                int k = k0 + kg * 4;
                float a0 = xb[(size_t)(k + 0) * N_ + n0 + n];
                float a1 = xb[(size_t)(k + 1) * N_ + n0 + n];
                float a2 = xb[(size_t)(k + 2) * N_ + n0 + n];
                float a3 = xb[(size_t)(k + 3) * N_ + n0 + n];
                uint32_t lo = packbf2(a0, a1), hi = packbf2(a2, a3);
                uint32_t d = xt_b + n * PROW2 + kg * 8;
                asm volatile("st.shared.v2.b32 [%0], {%1, %2};" :: "r"(d), "r"(lo), "r"(hi));
            }
        }
        __syncthreads();

#pragma unroll
        for (int kc = 0; kc < 4; kc++) {
            {
                uint32_t xa[4];
                ldsm4(xa, xaddrA + kc * 32);
                uint32_t wb0[4], wb1[4];
                ldsm4(wb0, qwaddr + kc * 32);
                ldsm4(wb1, qwaddr + 16 * PROW2 + kc * 32);
                mma16816(accq[0], xa, wb0[0], wb0[1]);
                mma16816(accq[1], xa, wb0[2], wb0[3]);
                mma16816(accq[2], xa, wb1[0], wb1[1]);
                mma16816(accq[3], xa, wb1[2], wb1[3]);
            }
            if (!isK) {
                uint32_t af[2][4];
#pragma unroll
                for (int t = 0; t < 2; t++)
                    ldsm4(af[t], waddr + t * 16 * PROW2 + kc * 32);
#pragma unroll
                for (int np = 0; np < 8; np++) {
                    uint32_t xb4[4];
                    ldsm4(xb4, xaddrB + np * 16 * PROW2 + kc * 32);
#pragma unroll
                    for (int t = 0; t < 2; t++) {
                        mma16816(accv[t][2 * np],     af[t], xb4[0], xb4[1]);
                        mma16816(accv[t][2 * np + 1], af[t], xb4[2], xb4[3]);
                    }
                }
            }
        }
    }

    {
        __nv_bfloat16* dst = (isK ? g_k + (size_t)(z - K_ * B_) * N_ * C8_
                                  : g_q + (size_t)z * N_ * C8_) + (size_t)n0 * C8_;
        int n = wid * 16 + g;
#pragma unroll
        for (int j = 0; j < 4; j++) {
            int o = j * 8 + 2 * m;
            *(uint32_t*)(dst + (size_t)n * C8_ + o)       = packbf2(accq[j][0], accq[j][1]);
            *(uint32_t*)(dst + (size_t)(n + 8) * C8_ + o) = packbf2(accq[j][2], accq[j][3]);
        }
    }
    if (!isK) {
        __nv_bfloat16* outb = g_v + (size_t)z * C_ * N_;
#pragma unroll
        for (int t = 0; t < 2; t++) {
            int c0 = wrowv + t * 16 + g;
#pragma unroll
            for (int nt = 0; nt < 16; nt++) {
                int n = n0 + nt * 8 + 2 * m;
                *(uint32_t*)(outb + (size_t)c0 * N_ + n)       = packbf2(accv[t][nt][0], accv[t][nt][1]);
                *(uint32_t*)(outb + (size_t)(c0 + 8) * N_ + n) = packbf2(accv[t][nt][2], accv[t][nt][3]);
            }
        }
    }
}

// ---------------------------------------------------------------------------
// prep_wf: fold gamma into W_acc, split W_x into bf16 hi/lo. grid 256 x 128thr.
__global__ void __launch_bounds__(128) prep_wf(const float* __restrict__ Wf,
                                               const float* __restrict__ gptr) {
    int o = blockIdx.x;
    int c4 = threadIdx.x * 4;
    float gamma = gptr[0];
    float4 w = *(const float4*)(Wf + (size_t)o * 512 + c4);
    if (c4 < 256) {
        uint32_t lo = packbf2(gamma * w.x, gamma * w.y);
        uint32_t hi = packbf2(gamma * w.z, gamma * w.w);
        *(uint32_t*)(g_wfa + (size_t)o * 256 + c4) = lo;
        *(uint32_t*)(g_wfa + (size_t)o * 256 + c4 + 2) = hi;
    } else {
        int c = c4 - 256;
        float h0 = __bfloat162float(__float2bfloat16(w.x));
        float h1 = __bfloat162float(__float2bfloat16(w.y));
        float h2 = __bfloat162float(__float2bfloat16(w.z));
        float h3 = __bfloat162float(__float2bfloat16(w.w));
        *(uint32_t*)(g_wfx_hi + (size_t)o * 256 + c)     = packbf2(w.x, w.y);
        *(uint32_t*)(g_wfx_hi + (size_t)o * 256 + c + 2) = packbf2(w.z, w.w);
        *(uint32_t*)(g_wfx_lo + (size_t)o * 256 + c)     = packbf2(w.x - h0, w.y - h1);
        *(uint32_t*)(g_wfx_lo + (size_t)o * 256 + c + 2) = packbf2(w.z - h2, w.w - h3);
    }
}

// ---------------------------------------------------------------------------
// prep_x: sum acc slabs + split x_f, transposed to [b][n][c] bf16.
// grid (N/64, C/64, B), 256 threads, 64x64 tile transpose through smem.
constexpr int TPS = 72;   // smem stride (bf16 elements)

__global__ void __launch_bounds__(256) prep_x(const float* __restrict__ xf) {
    __shared__ __nv_bfloat16 s_acc[64 * TPS], s_hi[64 * TPS], s_lo[64 * TPS];
    int tid = threadIdx.x;
    int nb = blockIdx.x * 64, cb = blockIdx.y * 64, b = blockIdx.z;
    const float* a0 = g_acc + ((size_t)(0 * B_ + b) * C_ + cb) * N_ + nb;
    const float* a1 = g_acc + ((size_t)(1 * B_ + b) * C_ + cb) * N_ + nb;
    const float* a2 = g_acc + ((size_t)(2 * B_ + b) * C_ + cb) * N_ + nb;
    const float* xp = xf + ((size_t)b * C_ + cb) * N_ + nb;

    int row = tid >> 2;              // c-local 0..63
    int col0 = (tid & 3) * 16;       // n-local start
#pragma unroll
    for (int j = 0; j < 4; j++) {
        int col = col0 + j * 4;
        float4 v0 = *(const float4*)(a0 + (size_t)row * N_ + col);
        float4 v1 = *(const float4*)(a1 + (size_t)row * N_ + col);
        float4 v2 = *(const float4*)(a2 + (size_t)row * N_ + col);
        float4 xv = *(const float4*)(xp + (size_t)row * N_ + col);
        float sv[4] = {v0.x + v1.x + v2.x, v0.y + v1.y + v2.y,
                       v0.z + v1.z + v2.z, v0.w + v1.w + v2.w};
        float xa[4] = {xv.x, xv.y, xv.z, xv.w};
#pragma unroll
        for (int e = 0; e < 4; e++) {
            s_acc[row * TPS + col + e] = __float2bfloat16(sv[e]);
            float h = __bfloat162float(__float2bfloat16(xa[e]));
            s_hi[row * TPS + col + e] = __float2bfloat16(xa[e]);
            s_lo[row * TPS + col + e] = __float2bfloat16(xa[e] - h);
        }
    }
    __syncthreads();

    int n = tid >> 2;                // n-local 0..63
    int c0 = (tid & 3) * 16;         // c-local start
    size_t off = ((size_t)b * N_ + nb + n) * 256 + cb + c0;
    __nv_bfloat16 tA[16], tH[16], tL[16];
#pragma unroll
    for (int j = 0; j < 16; j++) {
        tA[j] = s_acc[(c0 + j) * TPS + n];
        tH[j] = s_hi[(c0 + j) * TPS + n];
        tL[j] = s_lo[(c0 + j) * TPS + n];
    }
    *(uint4*)(g_accb + off)     = ((uint4*)tA)[0];
    *(uint4*)(g_accb + off + 8) = ((uint4*)tA)[1];
    *(uint4*)(g_xhi + off)      = ((uint4*)tH)[0];
    *(uint4*)(g_xhi + off + 8)  = ((uint4*)tH)[1];
    *(uint4*)(g_xlo + off)      = ((uint4*)tL)[0];
    *(uint4*)(g_xlo + off + 8)  = ((uint4*)tL)[1];
}

// ---------------------------------------------------------------------------
// final_gemm v2: pure bf16 cp.async double-buffered GEMM over virtual k=1024.
constexpr int FROW = 144;
constexpr int FX   = 128 * FROW;       // x tile offset within buffer (18432)
constexpr int FBUF = 2 * 128 * FROW;   // 36864 per buffer
constexpr int SMF_TOTAL = 2 * FBUF;    // 73728

__global__ void __launch_bounds__(128, 2) final_gemm(const float* __restrict__ bfv,
                                                     float* __restrict__ out) {
    extern __shared__ char fsm[];
    uint32_t sb = smem_u32(fsm);
    int tid = threadIdx.x, wid = tid >> 5, lane = tid & 31;
    int g = lane >> 2, m = lane & 3;
    int b = blockIdx.z;
    int obase = blockIdx.y * 128;
    int n0 = blockIdx.x * 128;
    int wrow = wid * 32;

    uint32_t woff = (wrow + (lane & 15)) * FROW + ((lane >> 4) & 1) * 16;
    uint32_t xoff = FX + ((lane >> 4) * 8 + (lane & 7)) * FROW + ((lane >> 3) & 1) * 16;

    float acc[2][16][4];
#pragma unroll
    for (int t = 0; t < 2; t++) {
        float b0 = bfv[obase + wrow + t * 16 + g];
        float b1 = bfv[obase + wrow + t * 16 + g + 8];
#pragma unroll
        for (int nt = 0; nt < 16; nt++) {
            acc[t][nt][0] = b0; acc[t][nt][1] = b0;
            acc[t][nt][2] = b1; acc[t][nt][3] = b1;
        }
    }

    auto load_step = [&](int ks, uint32_t bufb) {
        int bs = ks >> 2, c64 = (ks & 3) * 64;
        const __nv_bfloat16* wp = (bs == 0) ? g_wfa : (bs == 3) ? g_wfx_lo : g_wfx_hi;
        const __nv_bfloat16* xp = ((bs == 0) ? g_accb : (bs == 2) ? g_xlo : g_xhi)
                                  + (size_t)b * N_ * 256;
#pragma unroll
        for (int i = 0; i < 8; i++) {
            int idx = tid + 128 * i;
            int r = idx >> 3, ch = idx & 7;
            cp16(bufb + r * FROW + ch * 16,
                 wp + (size_t)(obase + r) * 256 + c64 + ch * 8);
            cp16(bufb + FX + r * FROW + ch * 16,
                 xp + (size_t)(n0 + r) * 256 + c64 + ch * 8);
        }
    };

    load_step(0, sb);
    CP_COMMIT();

    for (int ks = 0; ks < 16; ks++) {
        uint32_t bufb = sb + (ks & 1) * FBUF;
        if (ks + 1 < 16) load_step(ks + 1, sb + ((ks + 1) & 1) * FBUF);
        CP_COMMIT();
        CP_WAIT1();
        __syncthreads();

#pragma unroll
        for (int kc = 0; kc < 4; kc++) {
            uint32_t af[2][4];
#pragma unroll
            for (int t = 0; t < 2; t++)
                ldsm4(af[t], bufb + woff + t * 16 * FROW + kc * 32);
#pragma unroll
            for (int np = 0; np < 8; np++) {
                uint32_t xb4[4];
                ldsm4(xb4, bufb + xoff + np * 16 * FROW + kc * 32);
#pragma unroll
                for (int t = 0; t < 2; t++) {
                    mma16816(acc[t][2 * np],     af[t], xb4[0], xb4[1]);
                    mma16816(acc[t][2 * np + 1], af[t], xb4[2], xb4[3]);
                }
            }
        }
        __syncthreads();
    }

#pragma unroll
    for (int t = 0; t < 2; t++) {
        int o0 = obase + wrow + t * 16 + g;
#pragma unroll
        for (int nt = 0; nt < 16; nt++) {
            int n = n0 + nt * 8 + 2 * m;
            float* p = out + ((size_t)b * C_ + o0) * N_ + n;
            float* q = p + 8 * N_;
            p[0] = acc[t][nt][0]; p[1] = acc[t][nt][1];
            q[0] = acc[t][nt][2]; q[1] = acc[t][nt][3];
        }
    }
}

// ---------------------------------------------------------------------------
extern "C" void kernel_launch(void* const* d_in, const int* in_sizes, int n_in,
                              void* d_out, int out_size) {
    const float* x_f = (const float*)d_in[0];
    const float* x_b = (const float*)d_in[1];
    const float* Wq  = (const float*)d_in[2];
    const float* bq  = (const float*)d_in[3];
    const float* Wk  = (const float*)d_in[4];
    const float* bk  = (const float*)d_in[5];
    const float* Wv  = (const float*)d_in[6];
    const float* bv  = (const float*)d_in[7];
    const float* Wf  = (const float*)d_in[8];
    const float* bf  = (const float*)d_in[9];
    const float* gm  = (const float*)d_in[10];
    float* out = (float*)d_out;

    cudaFuncSetAttribute(attn_kernel, cudaFuncAttributeMaxDynamicSharedMemorySize, SM_TOTAL);
    cudaFuncSetAttribute(proj_all, cudaFuncAttributeMaxDynamicSharedMemorySize, SMP_TOTAL);
    cudaFuncSetAttribute(final_gemm, cudaFuncAttributeMaxDynamicSharedMemorySize, SMF_TOTAL);

    prep_wf<<<256, 128>>>(Wf, gm);
    proj_all<<<dim3(N_ / 128, 1, K_ * B_ + B_), 256, SMP_TOTAL>>>(x_b, x_f, Wq, bq, Wk, bk, Wv, bv);
    attn_kernel<<<dim3(N_ / TI, K_ * B_), 128, SM_TOTAL>>>();
    prep_x<<<dim3(N_ / 64, C_ / 64, B_), 256>>>(x_f);
    final_gemm<<<dim3(N_ / 128, C_ / 128, B_), 128, SMF_TOTAL>>>(bf, out);
}

// round 16
// speedup vs baseline: 1.4457x; 1.0434x over previous
#include <cuda_runtime.h>
#include <cuda_bf16.h>
#include <cstdint>
#include <math.h>

constexpr int B_  = 4;
constexpr int C_  = 256;
constexpr int C8_ = 32;
constexpr int N_  = 4096;
constexpr int K_  = 3;

constexpr int TI = 64;    // queries per CTA
constexpr int TJ = 64;    // keys per j-step
constexpr int NSTEP = N_ / TJ;

// ---- scratch (device globals; no allocation allowed) ----------------------
__device__ __nv_bfloat16 g_q[(size_t)K_ * B_ * N_ * C8_];   // [zb][n][o]
__device__ __nv_bfloat16 g_k[(size_t)B_ * N_ * C8_];        // [b][n][o]
__device__ __nv_bfloat16 g_v[(size_t)K_ * B_ * C_ * N_];    // [zb][c][n]
__device__ float         g_acc[(size_t)K_ * B_ * C_ * N_];  // [zb][c][n] per-kk slabs
// precomputed bf16 weights
__device__ __nv_bfloat16 g_wvb[256 * 256];                  // Wv bf16 [c][k]
__device__ __nv_bfloat16 g_wqb[32 * 256];                   // Wq bf16 [o][k]
__device__ __nv_bfloat16 g_wkb[32 * 256];                   // Wk bf16 [o][k]
__device__ __nv_bfloat16 g_wfa[256 * 256];                  // gamma * Wf[:, :256]
__device__ __nv_bfloat16 g_wfx_hi[256 * 256];               // hi(Wf[:, 256:])
__device__ __nv_bfloat16 g_wfx_lo[256 * 256];               // lo(Wf[:, 256:])
__device__ __nv_bfloat16 g_accb[(size_t)B_ * N_ * C_];      // [b][n][c] bf16(sum acc)
__device__ __nv_bfloat16 g_xhi [(size_t)B_ * N_ * C_];      // [b][n][c]
__device__ __nv_bfloat16 g_xlo [(size_t)B_ * N_ * C_];      // [b][n][c]

// ---- helpers --------------------------------------------------------------
__device__ __forceinline__ uint32_t smem_u32(const void* p) {
    uint32_t a;
    asm("{ .reg .u64 t; cvta.to.shared.u64 t, %1; cvt.u32.u64 %0, t; }" : "=r"(a) : "l"(p));
    return a;
}
__device__ __forceinline__ void ldsm4(uint32_t* r, uint32_t addr) {
    asm volatile("ldmatrix.sync.aligned.m8n8.x4.shared.b16 {%0,%1,%2,%3}, [%4];"
                 : "=r"(r[0]), "=r"(r[1]), "=r"(r[2]), "=r"(r[3]) : "r"(addr));
}
__device__ __forceinline__ void mma16816(float* d, const uint32_t* a, uint32_t b0, uint32_t b1) {
    asm volatile("mma.sync.aligned.m16n8k16.row.col.f32.bf16.bf16.f32 "
                 "{%0,%1,%2,%3}, {%4,%5,%6,%7}, {%8,%9}, {%0,%1,%2,%3};"
                 : "+f"(d[0]), "+f"(d[1]), "+f"(d[2]), "+f"(d[3])
                 : "r"(a[0]), "r"(a[1]), "r"(a[2]), "r"(a[3]), "r"(b0), "r"(b1));
}
__device__ __forceinline__ uint32_t packbf2(float x, float y) {
    __nv_bfloat162 h = __float22bfloat162_rn(make_float2(x, y));
    return *(uint32_t*)&h;
}
__device__ __forceinline__ void cp16(uint32_t dst, const void* src) {
    asm volatile("cp.async.cg.shared.global [%0], [%1], 16;" :: "r"(dst), "l"(src));
}
#define CP_COMMIT() asm volatile("cp.async.commit_group;" ::: "memory")
#define CP_WAIT1()  asm volatile("cp.async.wait_group 1;" ::: "memory")

// ---- attn smem layout -----------------------------------------------------
constexpr int QROW = 80;
constexpr int KROW = 80;
constexpr int VROW = 144;
constexpr int SM_Q  = 0;
constexpr int SM_K0 = 5120;
constexpr int VOFF  = 64 * KROW;
constexpr int BUFD  = VOFF + C_ * VROW;        // 41984
constexpr int SM_TOTAL = SM_K0 + 2 * BUFD;     // 89088

// ---------------------------------------------------------------------------
// attention: grid (N/64, K*B); one (zb, itile) unit per CTA; plain stores.
// (unchanged — measured at its mma.sync MAC-rate floor)
__global__ void __launch_bounds__(128, 2) attn_kernel() {
    extern __shared__ char smem[];
    uint32_t sb = smem_u32(smem);
    int tid = threadIdx.x, wid = tid >> 5, lane = tid & 31;
    int g = lane >> 2, m = lane & 3;
    int zb = blockIdx.y;
    int b = zb & 3;
    int itile = blockIdx.x * TI;
    int wrow = wid * 16;

    uint32_t qaddr = sb + SM_Q + (wrow + (lane & 15)) * QROW + ((lane >> 4) & 1) * 16;
    uint32_t koff = ((lane >> 4) * 8 + (lane & 7)) * KROW + ((lane >> 3) & 1) * 16;
    uint32_t voff = VOFF + ((lane >> 4) * 8 + (lane & 7)) * VROW + ((lane >> 3) & 1) * 16;

    const __nv_bfloat16* kbase = g_k + (size_t)b * N_ * C8_;
    const __nv_bfloat16* vbase = g_v + (size_t)zb * C_ * N_;

    const __nv_bfloat16* qp = g_q + ((size_t)zb * N_ + itile) * C8_;
    for (int t = tid; t < 256; t += 128) {
        int r = t >> 2, ch = t & 3;
        *(uint4*)(smem + SM_Q + r * QROW + ch * 16) = *(const uint4*)(qp + r * C8_ + ch * 8);
    }

    {
        uint32_t bufb = sb + SM_K0;
#pragma unroll
        for (int i = 0; i < 2; i++) {
            int t = tid + 128 * i;
            int r = t >> 2, ch = t & 3;
            cp16(bufb + r * KROW + ch * 16, kbase + (size_t)r * C8_ + ch * 8);
        }
#pragma unroll
        for (int i = 0; i < 16; i++) {
            int t = tid + 128 * i;
            int c = t >> 3, ch = t & 7;
            cp16(bufb + VOFF + c * VROW + ch * 16, vbase + (size_t)c * N_ + ch * 8);
        }
        CP_COMMIT();
    }

    __syncthreads();
    uint32_t qa[2][4];
    ldsm4(qa[0], qaddr);
    ldsm4(qa[1], qaddr + 32);

    float Dn[32][4];
#pragma unroll
    for (int c = 0; c < 32; c++)
#pragma unroll
        for (int p = 0; p < 4; p++) Dn[c][p] = 0.f;
    float den0 = 0.f, den1 = 0.f;

    for (int js = 0; js < NSTEP; js++) {
        uint32_t bufb = sb + SM_K0 + (js & 1) * BUFD;
        if (js + 1 < NSTEP) {
            int jt2 = (js + 1) * TJ;
            uint32_t nb = sb + SM_K0 + ((js + 1) & 1) * BUFD;
#pragma unroll
            for (int i = 0; i < 2; i++) {
                int t = tid + 128 * i;
                int r = t >> 2, ch = t & 3;
                cp16(nb + r * KROW + ch * 16, kbase + (size_t)(jt2 + r) * C8_ + ch * 8);
            }
#pragma unroll
            for (int i = 0; i < 16; i++) {
                int t = tid + 128 * i;
                int c = t >> 3, ch = t & 7;
                cp16(nb + VOFF + c * VROW + ch * 16, vbase + (size_t)c * N_ + jt2 + ch * 8);
            }
        }
        CP_COMMIT();
        CP_WAIT1();
        __syncthreads();

        float s[8][4];
#pragma unroll
        for (int j = 0; j < 8; j++)
#pragma unroll
            for (int p = 0; p < 4; p++) s[j][p] = 0.f;
#pragma unroll
        for (int kc = 0; kc < 2; kc++) {
#pragma unroll
            for (int jp = 0; jp < 4; jp++) {
                uint32_t kb[4];
                ldsm4(kb, bufb + koff + jp * 16 * KROW + kc * 32);
                mma16816(s[2 * jp],     qa[kc], kb[0], kb[1]);
                mma16816(s[2 * jp + 1], qa[kc], kb[2], kb[3]);
            }
        }
        uint32_t pa[8], pb[8];
#pragma unroll
        for (int j = 0; j < 8; j++) {
            float e0 = __expf(s[j][0]), e1 = __expf(s[j][1]);
            float e2 = __expf(s[j][2]), e3 = __expf(s[j][3]);
            den0 += e0 + e1;
            den1 += e2 + e3;
            pa[j] = packbf2(e0, e1);
            pb[j] = packbf2(e2, e3);
        }
#pragma unroll
        for (int tp = 0; tp < 4; tp++) {
            uint32_t af[4] = {pa[2 * tp], pb[2 * tp], pa[2 * tp + 1], pb[2 * tp + 1]};
#pragma unroll
            for (int vp = 0; vp < 16; vp++) {
                uint32_t vb[4];
                ldsm4(vb, bufb + voff + vp * 16 * VROW + tp * 32);
                mma16816(Dn[2 * vp],     af, vb[0], vb[1]);
                mma16816(Dn[2 * vp + 1], af, vb[2], vb[3]);
            }
        }
        __syncthreads();
    }

    den0 += __shfl_xor_sync(0xffffffffu, den0, 1);
    den0 += __shfl_xor_sync(0xffffffffu, den0, 2);
    den1 += __shfl_xor_sync(0xffffffffu, den1, 1);
    den1 += __shfl_xor_sync(0xffffffffu, den1, 2);
    float inv0 = 1.f / den0, inv1 = 1.f / den1;

    float* accb = g_acc + (size_t)zb * C_ * N_;
    int n0 = itile + wrow + g;
#pragma unroll
    for (int ct = 0; ct < 32; ct++) {
        int c = 8 * ct + 2 * m;
        float* p0 = accb + (size_t)c * N_ + n0;
        float* p1 = p0 + N_;
        p0[0] = Dn[ct][0] * inv0;
        p1[0] = Dn[ct][1] * inv0;
        p0[8] = Dn[ct][2] * inv1;
        p1[8] = Dn[ct][3] * inv1;
    }
}

// ---------------------------------------------------------------------------
// prep_w: all weight conversions, once. grid 256, 128 threads.
__global__ void __launch_bounds__(128) prep_w(const float* __restrict__ Wf,
                                              const float* __restrict__ gptr,
                                              const float* __restrict__ Wq,
                                              const float* __restrict__ Wk,
                                              const float* __restrict__ Wv) {
    int o = blockIdx.x;
    int tid = threadIdx.x;
    float gamma = gptr[0];
    // Wf split (as before)
    {
        int c4 = tid * 4;
        float4 w = *(const float4*)(Wf + (size_t)o * 512 + c4);
        if (c4 < 256) {
            *(uint32_t*)(g_wfa + (size_t)o * 256 + c4)     = packbf2(gamma * w.x, gamma * w.y);
            *(uint32_t*)(g_wfa + (size_t)o * 256 + c4 + 2) = packbf2(gamma * w.z, gamma * w.w);
        } else {
            int c = c4 - 256;
            float h0 = __bfloat162float(__float2bfloat16(w.x));
            float h1 = __bfloat162float(__float2bfloat16(w.y));
            float h2 = __bfloat162float(__float2bfloat16(w.z));
            float h3 = __bfloat162float(__float2bfloat16(w.w));
            *(uint32_t*)(g_wfx_hi + (size_t)o * 256 + c)     = packbf2(w.x, w.y);
            *(uint32_t*)(g_wfx_hi + (size_t)o * 256 + c + 2) = packbf2(w.z, w.w);
            *(uint32_t*)(g_wfx_lo + (size_t)o * 256 + c)     = packbf2(w.x - h0, w.y - h1);
            *(uint32_t*)(g_wfx_lo + (size_t)o * 256 + c + 2) = packbf2(w.z - h2, w.w - h3);
        }
    }
    // Wv bf16 (row o, 256 cols / 128 thr = 2 each)
    {
        int c = tid * 2;
        float2 w = *(const float2*)(Wv + (size_t)o * 256 + c);
        *(uint32_t*)(g_wvb + (size_t)o * 256 + c) = packbf2(w.x, w.y);
    }
    // Wq / Wk bf16 (rows 0..31)
    if (o < 32) {
        int c = tid * 2;
        float2 wq = *(const float2*)(Wq + (size_t)o * 256 + c);
        float2 wk = *(const float2*)(Wk + (size_t)o * 256 + c);
        *(uint32_t*)(g_wqb + (size_t)o * 256 + c) = packbf2(wq.x, wq.y);
        *(uint32_t*)(g_wkb + (size_t)o * 256 + c) = packbf2(wk.x, wk.y);
    }
}

// ---------------------------------------------------------------------------
// proj_all v2: cp.async double-buffered (bf16 weights + fp32 x staging),
// x converted smem->smem. One xt transpose per (n0, z).
constexpr int PROW2 = 144;
constexpr int XSROW = 528;                       // 128 floats + 16B pad
constexpr int OFF_WV = 0;                        // 256 * 144 = 36864
constexpr int OFF_WQ = 36864;                    // 32 * 144  = 4608
constexpr int OFF_XS = 41472;                    // 64 * 528  = 33792
constexpr int PBUF   = 75264;                    // per-buffer
constexpr int OFF_XT = 2 * PBUF;                 // 150528; 128*144 = 18432
constexpr int SMP_TOTAL = OFF_XT + 128 * PROW2;  // 168960

__global__ void __launch_bounds__(256, 1) proj_all(const float* __restrict__ xball,
                                                   const float* __restrict__ xf,
                                                   const float* __restrict__ bq,
                                                   const float* __restrict__ bk,
                                                   const float* __restrict__ bv) {
    extern __shared__ char psm[];
    uint32_t sb = smem_u32(psm);
    uint32_t xt_b = sb + OFF_XT;
    int tid = threadIdx.x, wid = tid >> 5, lane = tid & 31;
    int g = lane >> 2, m = lane & 3;
    int z = blockIdx.z;
    int n0 = blockIdx.x * 128;
    bool isK = (z >= K_ * B_);
    const float* xb = isK ? (xf + (size_t)(z - K_ * B_) * C_ * N_)
                          : (xball + (size_t)z * C_ * N_);
    const __nv_bfloat16* Wqkb = isK ? g_wkb : g_wqb;
    const float* bqk = isK ? bk : bq;

    int wrowv = wid * 32;
    uint32_t woff = OFF_WV + (wrowv + (lane & 15)) * PROW2 + ((lane >> 4) & 1) * 16;
    uint32_t xoffB = ((lane >> 4) * 8 + (lane & 7)) * PROW2 + ((lane >> 3) & 1) * 16;
    uint32_t xoffA = (wid * 16 + (lane & 15)) * PROW2 + ((lane >> 4) & 1) * 16;
    uint32_t qwoff = OFF_WQ + ((lane >> 4) * 8 + (lane & 7)) * PROW2 + ((lane >> 3) & 1) * 16;

    float accv[2][16][4];
    if (!isK) {
#pragma unroll
        for (int t = 0; t < 2; t++) {
            float b0 = bv[wrowv + t * 16 + g];
            float b1 = bv[wrowv + t * 16 + g + 8];
#pragma unroll
            for (int nt = 0; nt < 16; nt++) {
                accv[t][nt][0] = b0; accv[t][nt][1] = b0;
                accv[t][nt][2] = b1; accv[t][nt][3] = b1;
            }
        }
    }
    float accq[4][4];
#pragma unroll
    for (int j = 0; j < 4; j++) {
        int o = j * 8 + 2 * m;
        float b0 = bqk[o], b1 = bqk[o + 1];
        accq[j][0] = b0; accq[j][1] = b1;
        accq[j][2] = b0; accq[j][3] = b1;
    }

    auto load_step = [&](int ks, uint32_t bufb) {
        int k0 = ks * 64;
        // Wv tile bf16 [256][64] (skip for k-only slabs)
        if (!isK) {
#pragma unroll
            for (int i = 0; i < 8; i++) {
                int idx = tid + 256 * i;
                int r = idx >> 3, ch = idx & 7;
                cp16(bufb + OFF_WV + r * PROW2 + ch * 16,
                     g_wvb + (size_t)r * 256 + k0 + ch * 8);
            }
        }
        // Wq/Wk tile bf16 [32][64]
        {
            int r = tid >> 3, ch = tid & 7;
            if (r < 32)
                cp16(bufb + OFF_WQ + r * PROW2 + ch * 16,
                     Wqkb + (size_t)r * 256 + k0 + ch * 8);
        }
        // x fp32 staging [64 k][128 n]
#pragma unroll
        for (int i = 0; i < 8; i++) {
            int idx = tid + 256 * i;
            int r = idx >> 5, ch = idx & 31;
            cp16(bufb + OFF_XS + r * XSROW + ch * 16,
                 xb + (size_t)(k0 + r) * N_ + n0 + ch * 4);
        }
    };

    load_step(0, sb);
    CP_COMMIT();

    for (int ks = 0; ks < 4; ks++) {
        uint32_t bufb = sb + (ks & 1) * PBUF;
        if (ks + 1 < 4) load_step(ks + 1, sb + ((ks + 1) & 1) * PBUF);
        CP_COMMIT();
        CP_WAIT1();
        __syncthreads();   // staging ready AND prior xt reads done

        // convert staging fp32 [k][n] -> xt bf16 [n][k] (smem->smem)
        {
            int n = tid & 127;
            int kgbase = (tid >> 7) * 8;
            const float* xs = (const float*)(psm + (ks & 1) * PBUF + OFF_XS);
#pragma unroll
            for (int kg2 = 0; kg2 < 8; kg2++) {
                int kg = kgbase + kg2;
                int k4 = kg * 4;
                float a0 = xs[(k4 + 0) * 132 + n];
                float a1 = xs[(k4 + 1) * 132 + n];
                float a2 = xs[(k4 + 2) * 132 + n];
                float a3 = xs[(k4 + 3) * 132 + n];
                uint32_t lo = packbf2(a0, a1), hi = packbf2(a2, a3);
                uint32_t d = xt_b + n * PROW2 + kg * 8;
                asm volatile("st.shared.v2.b32 [%0], {%1, %2};" :: "r"(d), "r"(lo), "r"(hi));
            }
        }
        __syncthreads();

#pragma unroll
        for (int kc = 0; kc < 4; kc++) {
            // q phase: A = xt rows (n), B = Wq/Wk
            {
                uint32_t xa[4];
                ldsm4(xa, xt_b + xoffA + kc * 32);
                uint32_t wb0[4], wb1[4];
                ldsm4(wb0, bufb + qwoff + kc * 32);
                ldsm4(wb1, bufb + qwoff + 16 * PROW2 + kc * 32);
                mma16816(accq[0], xa, wb0[0], wb0[1]);
                mma16816(accq[1], xa, wb0[2], wb0[3]);
                mma16816(accq[2], xa, wb1[0], wb1[1]);
                mma16816(accq[3], xa, wb1[2], wb1[3]);
            }
            // v phase: A = Wv rows (c), B = xt
            if (!isK) {
                uint32_t af[2][4];
#pragma unroll
                for (int t = 0; t < 2; t++)
                    ldsm4(af[t], bufb + woff + t * 16 * PROW2 + kc * 32);
#pragma unroll
                for (int np = 0; np < 8; np++) {
                    uint32_t xb4[4];
                    ldsm4(xb4, xt_b + xoffB + np * 16 * PROW2 + kc * 32);
#pragma unroll
                    for (int t = 0; t < 2; t++) {
                        mma16816(accv[t][2 * np],     af[t], xb4[0], xb4[1]);
                        mma16816(accv[t][2 * np + 1], af[t], xb4[2], xb4[3]);
                    }
                }
            }
        }
    }

    {
        __nv_bfloat16* dst = (isK ? g_k + (size_t)(z - K_ * B_) * N_ * C8_
                                  : g_q + (size_t)z * N_ * C8_) + (size_t)n0 * C8_;
        int n = wid * 16 + g;
#pragma unroll
        for (int j = 0; j < 4; j++) {
            int o = j * 8 + 2 * m;
            *(uint32_t*)(dst + (size_t)n * C8_ + o)       = packbf2(accq[j][0], accq[j][1]);
            *(uint32_t*)(dst + (size_t)(n + 8) * C8_ + o) = packbf2(accq[j][2], accq[j][3]);
        }
    }
    if (!isK) {
        __nv_bfloat16* outb = g_v + (size_t)z * C_ * N_;
#pragma unroll
        for (int t = 0; t < 2; t++) {
            int c0 = wrowv + t * 16 + g;
#pragma unroll
            for (int nt = 0; nt < 16; nt++) {
                int n = n0 + nt * 8 + 2 * m;
                *(uint32_t*)(outb + (size_t)c0 * N_ + n)       = packbf2(accv[t][nt][0], accv[t][nt][1]);
                *(uint32_t*)(outb + (size_t)(c0 + 8) * N_ + n) = packbf2(accv[t][nt][2], accv[t][nt][3]);
            }
        }
    }
}

// ---------------------------------------------------------------------------
// prep_x: sum acc slabs + split x_f, transposed to [b][n][c] bf16.
// TPS=65: c-group byte offsets {0,32,64,96} mod 128 -> conflict-free loads.
constexpr int TPS = 65;

__global__ void __launch_bounds__(256) prep_x(const float* __restrict__ xf) {
    __shared__ __nv_bfloat16 s_acc[64 * TPS], s_hi[64 * TPS], s_lo[64 * TPS];
    int tid = threadIdx.x;
    int nb = blockIdx.x * 64, cb = blockIdx.y * 64, b = blockIdx.z;
    const float* a0 = g_acc + ((size_t)(0 * B_ + b) * C_ + cb) * N_ + nb;
    const float* a1 = g_acc + ((size_t)(1 * B_ + b) * C_ + cb) * N_ + nb;
    const float* a2 = g_acc + ((size_t)(2 * B_ + b) * C_ + cb) * N_ + nb;
    const float* xp = xf + ((size_t)b * C_ + cb) * N_ + nb;

    int row = tid >> 2;
    int col0 = (tid & 3) * 16;
#pragma unroll
    for (int j = 0; j < 4; j++) {
        int col = col0 + j * 4;
        float4 v0 = *(const float4*)(a0 + (size_t)row * N_ + col);
        float4 v1 = *(const float4*)(a1 + (size_t)row * N_ + col);
        float4 v2 = *(const float4*)(a2 + (size_t)row * N_ + col);
        float4 xv = *(const float4*)(xp + (size_t)row * N_ + col);
        float sv[4] = {v0.x + v1.x + v2.x, v0.y + v1.y + v2.y,
                       v0.z + v1.z + v2.z, v0.w + v1.w + v2.w};
        float xa[4] = {xv.x, xv.y, xv.z, xv.w};
#pragma unroll
        for (int e = 0; e < 4; e++) {
            s_acc[row * TPS + col + e] = __float2bfloat16(sv[e]);
            float h = __bfloat162float(__float2bfloat16(xa[e]));
            s_hi[row * TPS + col + e] = __float2bfloat16(xa[e]);
            s_lo[row * TPS + col + e] = __float2bfloat16(xa[e] - h);
        }
    }
    __syncthreads();

    int n = tid >> 2;
    int c0 = (tid & 3) * 16;
    size_t off = ((size_t)b * N_ + nb + n) * 256 + cb + c0;
    __nv_bfloat16 tA[16], tH[16], tL[16];
#pragma unroll
    for (int j = 0; j < 16; j++) {
        tA[j] = s_acc[(c0 + j) * TPS + n];
        tH[j] = s_hi[(c0 + j) * TPS + n];
        tL[j] = s_lo[(c0 + j) * TPS + n];
    }
    *(uint4*)(g_accb + off)     = ((uint4*)tA)[0];
    *(uint4*)(g_accb + off + 8) = ((uint4*)tA)[1];
    *(uint4*)(g_xhi + off)      = ((uint4*)tH)[0];
    *(uint4*)(g_xhi + off + 8)  = ((uint4*)tH)[1];
    *(uint4*)(g_xlo + off)      = ((uint4*)tL)[0];
    *(uint4*)(g_xlo + off + 8)  = ((uint4*)tL)[1];
}

// ---------------------------------------------------------------------------
// final_gemm: pure bf16 cp.async double-buffered GEMM over virtual k=1024.
constexpr int FROW = 144;
constexpr int FX   = 128 * FROW;
constexpr int FBUF = 2 * 128 * FROW;
constexpr int SMF_TOTAL = 2 * FBUF;

__global__ void __launch_bounds__(128, 2) final_gemm(const float* __restrict__ bfv,
                                                     float* __restrict__ out) {
    extern __shared__ char fsm[];
    uint32_t sb = smem_u32(fsm);
    int tid = threadIdx.x, wid = tid >> 5, lane = tid & 31;
    int g = lane >> 2, m = lane & 3;
    int b = blockIdx.z;
    int obase = blockIdx.y * 128;
    int n0 = blockIdx.x * 128;
    int wrow = wid * 32;

    uint32_t woff = (wrow + (lane & 15)) * FROW + ((lane >> 4) & 1) * 16;
    uint32_t xoff = FX + ((lane >> 4) * 8 + (lane & 7)) * FROW + ((lane >> 3) & 1) * 16;

    float acc[2][16][4];
#pragma unroll
    for (int t = 0; t < 2; t++) {
        float b0 = bfv[obase + wrow + t * 16 + g];
        float b1 = bfv[obase + wrow + t * 16 + g + 8];
#pragma unroll
        for (int nt = 0; nt < 16; nt++) {
            acc[t][nt][0] = b0; acc[t][nt][1] = b0;
            acc[t][nt][2] = b1; acc[t][nt][3] = b1;
        }
    }

    auto load_step = [&](int ks, uint32_t bufb) {
        int bs = ks >> 2, c64 = (ks & 3) * 64;
        const __nv_bfloat16* wp = (bs == 0) ? g_wfa : (bs == 3) ? g_wfx_lo : g_wfx_hi;
        const __nv_bfloat16* xp = ((bs == 0) ? g_accb : (bs == 2) ? g_xlo : g_xhi)
                                  + (size_t)b * N_ * 256;
#pragma unroll
        for (int i = 0; i < 8; i++) {
            int idx = tid + 128 * i;
            int r = idx >> 3, ch = idx & 7;
            cp16(bufb + r * FROW + ch * 16,
                 wp + (size_t)(obase + r) * 256 + c64 + ch * 8);
            cp16(bufb + FX + r * FROW + ch * 16,
                 xp + (size_t)(n0 + r) * 256 + c64 + ch * 8);
        }
    };

    load_step(0, sb);
    CP_COMMIT();

    for (int ks = 0; ks < 16; ks++) {
        uint32_t bufb = sb + (ks & 1) * FBUF;
        if (ks + 1 < 16) load_step(ks + 1, sb + ((ks + 1) & 1) * FBUF);
        CP_COMMIT();
        CP_WAIT1();
        __syncthreads();

#pragma unroll
        for (int kc = 0; kc < 4; kc++) {
            uint32_t af[2][4];
#pragma unroll
            for (int t = 0; t < 2; t++)
                ldsm4(af[t], bufb + woff + t * 16 * FROW + kc * 32);
#pragma unroll
            for (int np = 0; np < 8; np++) {
                uint32_t xb4[4];
                ldsm4(xb4, bufb + xoff + np * 16 * FROW + kc * 32);
#pragma unroll
                for (int t = 0; t < 2; t++) {
                    mma16816(acc[t][2 * np],     af[t], xb4[0], xb4[1]);
                    mma16816(acc[t][2 * np + 1], af[t], xb4[2], xb4[3]);
                }
            }
        }
        __syncthreads();
    }

#pragma unroll
    for (int t = 0; t < 2; t++) {
        int o0 = obase + wrow + t * 16 + g;
#pragma unroll
        for (int nt = 0; nt < 16; nt++) {
            int n = n0 + nt * 8 + 2 * m;
            float* p = out + ((size_t)b * C_ + o0) * N_ + n;
            float* q = p + 8 * N_;
            p[0] = acc[t][nt][0]; p[1] = acc[t][nt][1];
            q[0] = acc[t][nt][2]; q[1] = acc[t][nt][3];
        }
    }
}

// ---------------------------------------------------------------------------
extern "C" void kernel_launch(void* const* d_in, const int* in_sizes, int n_in,
                              void* d_out, int out_size) {
    const float* x_f = (const float*)d_in[0];
    const float* x_b = (const float*)d_in[1];
    const float* Wq  = (const float*)d_in[2];
    const float* bq  = (const float*)d_in[3];
    const float* Wk  = (const float*)d_in[4];
    const float* bk  = (const float*)d_in[5];
    const float* Wv  = (const float*)d_in[6];
    const float* bv  = (const float*)d_in[7];
    const float* Wf  = (const float*)d_in[8];
    const float* bf  = (const float*)d_in[9];
    const float* gm  = (const float*)d_in[10];
    float* out = (float*)d_out;

    cudaFuncSetAttribute(attn_kernel, cudaFuncAttributeMaxDynamicSharedMemorySize, SM_TOTAL);
    cudaFuncSetAttribute(proj_all, cudaFuncAttributeMaxDynamicSharedMemorySize, SMP_TOTAL);
    cudaFuncSetAttribute(final_gemm, cudaFuncAttributeMaxDynamicSharedMemorySize, SMF_TOTAL);

    prep_w<<<256, 128>>>(Wf, gm, Wq, Wk, Wv);
    proj_all<<<dim3(N_ / 128, 1, K_ * B_ + B_), 256, SMP_TOTAL>>>(x_b, x_f, bq, bk, bv);
    attn_kernel<<<dim3(N_ / TI, K_ * B_), 128, SM_TOTAL>>>();
    prep_x<<<dim3(N_ / 64, C_ / 64, B_), 256>>>(x_f);
    final_gemm<<<dim3(N_ / 128, C_ / 128, B_), 128, SMF_TOTAL>>>(bf, out);
}